// round 14
// baseline (speedup 1.0000x reference)
#include <cuda_runtime.h>
#include <cuda_bf16.h>
#include <cstdint>
#include <cstddef>

// ---------------------------------------------------------------------------
// GHM — tcgen05 pipeline v11: v10 with 1024-thread sweep kernels
// (fills halved per thread, TMEM epilogues LDTM.x8 over 32 warps).
// ---------------------------------------------------------------------------

#if defined(__CUDA_ARCH_FEAT_SM103_ALL) || defined(__CUDA_ARCH_FEAT_SM100_ALL)
#define TC05_OK 1
#else
#define TC05_OK 0
#endif

#define NMAX 200000
#define HDIM 256
#define MDIM 64
#define NTH  1024
#define AITER (2048 / NTH)
#define SPGRID 148
#define MAXCTA 1600

__device__ float g_Hf [(size_t)NMAX * HDIM];
__device__ float g_X  [(size_t)NMAX * HDIM];
__device__ float g_Wt [(size_t)NMAX * MDIM];
__device__ float g_part[(size_t)SPGRID * HDIM * MDIM];
__device__ float g_mp [(size_t)MAXCTA * HDIM];
#define WB_FF1 0
#define WB_WA  262144
#define WB_WB  524288
#define WB_FF2 589824
#define WB_BLK 1114112
__device__ __align__(16) char g_wsw[2 * WB_BLK];
__device__ __align__(16) char g_sgsw[65536];     // Sg^T tile, Nc=256, K=64

__device__ __forceinline__ float gelu_f(float x) {
    return 0.5f * x * (1.0f + erff(x * 0.70710678118654752440f));
}
__device__ __forceinline__ uint32_t packbf(float lo, float hi) {
    uint32_t r;
    asm("cvt.rn.bf16x2.f32 %0, %1, %2;" : "=r"(r) : "f"(hi), "f"(lo));
    return r;
}
__device__ __forceinline__ void split2(float f0, float f1, uint32_t& h, uint32_t& l) {
    h = packbf(f0, f1);
    float fx = __uint_as_float(h << 16), fy = __uint_as_float(h & 0xffff0000u);
    l = packbf(f0 - fx, f1 - fy);
}

#define SWZ(b) ((b) ^ (((b) >> 3) & 0x70))

// fallback-only weight reconstruct
__device__ __forceinline__ float wval(const char* w, int Nc, int n, int k) {
    int ch = k >> 6, kk = k & 63;
    const char* base = w + (size_t)ch * Nc * 256;
    uint32_t so = SWZ(n * 128 + kk * 2);
    return __bfloat162float(*(const __nv_bfloat16*)(base + so)) +
           __bfloat162float(*(const __nv_bfloat16*)(base + Nc * 128 + so));
}

#if TC05_OK
__device__ __forceinline__ uint32_t elect_one_pred() {
    uint32_t pred;
    asm volatile("{\n\t.reg .pred p;\n\telect.sync _|p, 0xFFFFFFFF;\n\t"
                 "selp.b32 %0, 1, 0, p;\n\t}" : "=r"(pred));
    return pred;
}
__device__ __forceinline__ uint32_t smem_to_u32(const void* p) {
    uint32_t a;
    asm("{ .reg .u64 t; cvta.to.shared.u64 t, %1; cvt.u32.u64 %0, t; }"
        : "=r"(a) : "l"(p));
    return a;
}
#define TCGEN05_ALLOC(sa, n) \
    asm volatile("tcgen05.alloc.cta_group::1.sync.aligned.shared::cta.b32 [%0], %1;" \
                 :: "r"((uint32_t)(sa)), "r"((uint32_t)(n)) : "memory")
#define TCGEN05_DEALLOC(ta, n) \
    asm volatile("tcgen05.dealloc.cta_group::1.sync.aligned.b32 %0, %1;" \
                 :: "r"(ta), "r"((uint32_t)(n)))
#define TCGEN05_COMMIT(mb) \
    asm volatile("tcgen05.commit.cta_group::1.mbarrier::arrive::one.shared::cluster.b64 [%0];" \
                 :: "r"((uint32_t)(mb)) : "memory")
#define TCGEN05_WAIT_LD()  asm volatile("tcgen05.wait::ld.sync.aligned;" ::: "memory")
#define TCGEN05_FENCE_AFTER()  asm volatile("tcgen05.fence::after_thread_sync;" ::: "memory")
#define TCGEN05_FENCE_BEFORE() asm volatile("tcgen05.fence::before_thread_sync;" ::: "memory")
#define FENCE_ASYNC() asm volatile("fence.proxy.async.shared::cta;" ::: "memory")
#define MBARRIER_INIT(mb, c) \
    asm volatile("mbarrier.init.shared.b64 [%0], %1;" :: "r"((uint32_t)(mb)), "r"((uint32_t)(c)) : "memory")
#define MBARRIER_WAIT_PARITY(mb, ph) do { \
    uint32_t _m = (uint32_t)(mb), _p = (uint32_t)(ph), _d; \
    asm volatile("{\n\t.reg .pred p;\n\t" \
        "mbarrier.try_wait.parity.acquire.cta.shared::cta.b64 p, [%1], %2;\n\t" \
        "selp.b32 %0, 1, 0, p;\n\t}" : "=r"(_d) : "r"(_m), "r"(_p) : "memory"); \
    if (!_d) { \
        asm volatile("{\n\t.reg .pred P1;\n\tWL_%=: \n\t" \
            "mbarrier.try_wait.parity.acquire.cta.shared::cta.b64 P1, [%0], %1, 0x989680;\n\t" \
            "@P1 bra.uni WD_%=;\n\tbra.uni WL_%=;\n\tWD_%=: \n\t}" \
            :: "r"(_m), "r"(_p) : "memory"); \
    } } while (0)
#define TCGEN05_LD_X32(r, ta) \
    asm volatile("tcgen05.ld.sync.aligned.32x32b.x32.b32 " \
        "{%0,%1,%2,%3,%4,%5,%6,%7,%8,%9,%10,%11,%12,%13,%14,%15," \
        "%16,%17,%18,%19,%20,%21,%22,%23,%24,%25,%26,%27,%28,%29,%30,%31}, [%32];" \
        : "=r"((r)[0]),"=r"((r)[1]),"=r"((r)[2]),"=r"((r)[3]),"=r"((r)[4]),"=r"((r)[5]), \
          "=r"((r)[6]),"=r"((r)[7]),"=r"((r)[8]),"=r"((r)[9]),"=r"((r)[10]),"=r"((r)[11]), \
          "=r"((r)[12]),"=r"((r)[13]),"=r"((r)[14]),"=r"((r)[15]),"=r"((r)[16]),"=r"((r)[17]), \
          "=r"((r)[18]),"=r"((r)[19]),"=r"((r)[20]),"=r"((r)[21]),"=r"((r)[22]),"=r"((r)[23]), \
          "=r"((r)[24]),"=r"((r)[25]),"=r"((r)[26]),"=r"((r)[27]),"=r"((r)[28]),"=r"((r)[29]), \
          "=r"((r)[30]),"=r"((r)[31]) : "r"(ta))
#define TCGEN05_LD_X8(r, ta) \
    asm volatile("tcgen05.ld.sync.aligned.32x32b.x8.b32 " \
        "{%0,%1,%2,%3,%4,%5,%6,%7}, [%8];" \
        : "=r"((r)[0]),"=r"((r)[1]),"=r"((r)[2]),"=r"((r)[3]), \
          "=r"((r)[4]),"=r"((r)[5]),"=r"((r)[6]),"=r"((r)[7]) : "r"(ta))

static constexpr uint64_t SMEM_DESC_BASE_SW128 =
    (uint64_t(2) << 61) | (uint64_t(1) << 46) | (uint64_t(64) << 32) | (uint64_t(1) << 16);
#define MAKE_SMEM_DESC(a) (SMEM_DESC_BASE_SW128 | ((uint64_t)((a) >> 4) & 0x3FFF))

__device__ __forceinline__ void mma_f16_ss(uint32_t d, uint64_t ad, uint64_t bd,
                                           uint32_t idesc, uint32_t en) {
    asm volatile("{\n\t.reg .pred p;\n\tsetp.ne.u32 p, %5, 0;\n\t"
        "tcgen05.mma.cta_group::1.kind::f16 [%0], %1, %2, %3, {%4,%4,%4,%4}, p;\n\t}"
        :: "r"(d), "l"(ad), "l"(bd), "r"(idesc), "r"(0u), "r"(en) : "memory");
}

__device__ __forceinline__ void mma_chunk(uint32_t d, uint32_t sb_ah, uint32_t sb_bh,
                                          int aL, int bL, uint32_t idesc, bool first) {
    const uint64_t adh = MAKE_SMEM_DESC(sb_ah), adl = MAKE_SMEM_DESC(sb_ah + aL);
    const uint64_t bdh = MAKE_SMEM_DESC(sb_bh), bdl = MAKE_SMEM_DESC(sb_bh + bL);
    #pragma unroll
    for (int ks = 0; ks < 4; ks++) {
        uint64_t off = (uint64_t)(ks * 2);
        mma_f16_ss(d, adh + off, bdh + off, idesc, (first && ks == 0) ? 0u : 1u);
        mma_f16_ss(d, adh + off, bdl + off, idesc, 1u);
        mma_f16_ss(d, adl + off, bdh + off, idesc, 1u);
    }
}

__device__ __forceinline__ void fillB_async(uint32_t dst, const char* src,
                                            int bytes, int tid, int nth) {
    for (int o = tid * 16; o < bytes; o += nth * 16)
        asm volatile("cp.async.cg.shared.global [%0], [%1], 16;"
                     :: "r"(dst + o), "l"(src + o) : "memory");
}
#define CP_WAIT() asm volatile("cp.async.commit_group;\ncp.async.wait_group 0;" ::: "memory")
#endif // TC05_OK

#define IDESC(Nc) ((1u << 4) | (1u << 7) | (1u << 10) | ((uint32_t)((Nc) / 8) << 17) | (8u << 24))
#define AOFF(b)  (1024 + (b) * 32768)
#define BOFF(b)  (66560 + (b) * 65536)
#define FSMEM    197632
#define SPSMEM   (1024 + 2 * 81920)

#if TC05_OK
__device__ __forceinline__ void loadA4(float4* va, const float* A, int row0, int M,
                                       int strideK, int kc0, int t) {
    #pragma unroll
    for (int i = 0; i < AITER; i++) {
        int fid = t + i * NTH;
        int r = fid >> 4, c16 = fid & 15;
        int gr = row0 + r;
        va[i] = make_float4(0.f, 0.f, 0.f, 0.f);
        if (gr < M)
            va[i] = *reinterpret_cast<const float4*>(&A[(size_t)gr * strideK + kc0 + c16 * 4]);
    }
}
template<bool GELU_A>
__device__ __forceinline__ void storeA4(char* aB, const float4* va, int t) {
    #pragma unroll
    for (int i = 0; i < AITER; i++) {
        int fid = t + i * NTH;
        int r = fid >> 4, c16 = fid & 15;
        float4 v = va[i];
        if (GELU_A) { v.x = gelu_f(v.x); v.y = gelu_f(v.y); v.z = gelu_f(v.z); v.w = gelu_f(v.w); }
        uint32_t h0, l0, h1, l1;
        split2(v.x, v.y, h0, l0);
        split2(v.z, v.w, h1, l1);
        int swo = SWZ(r * 128 + c16 * 8);
        *reinterpret_cast<uint2*>(aB + swo)         = make_uint2(h0, h1);
        *reinterpret_cast<uint2*>(aB + 16384 + swo) = make_uint2(l0, l1);
    }
}
// 32-warp TMEM-sourced A-tile producer: warp w covers col segment (w>>2)*8,
// subpartition (w&3). dr = 8 values.
__device__ __forceinline__ void epiA8(char* aB, const uint32_t* dr, int w, int lane,
                                      const float* bias, int colBase,
                                      float* HfRow /*or null*/) {
    const int seg = w >> 2;
    const int r = (w & 3) * 32 + lane;
    #pragma unroll
    for (int q = 0; q < 2; q++) {
        float f0 = __uint_as_float(dr[4*q]);
        float f1 = __uint_as_float(dr[4*q+1]);
        float f2 = __uint_as_float(dr[4*q+2]);
        float f3 = __uint_as_float(dr[4*q+3]);
        if (bias) {
            int col = colBase + seg * 8 + 4 * q;
            f0 += bias[col]; f1 += bias[col+1]; f2 += bias[col+2]; f3 += bias[col+3];
        }
        f0 = gelu_f(f0); f1 = gelu_f(f1); f2 = gelu_f(f2); f3 = gelu_f(f3);
        if (HfRow)
            *reinterpret_cast<float4*>(&HfRow[colBase + seg * 8 + 4 * q]) =
                make_float4(f0, f1, f2, f3);
        uint32_t h0, l0, h1, l1;
        split2(f0, f1, h0, l0);
        split2(f2, f3, h1, l1);
        int off = SWZ(r * 128 + seg * 16 + q * 8);
        *reinterpret_cast<uint2*>(aB + off)         = make_uint2(h0, h1);
        *reinterpret_cast<uint2*>(aB + 16384 + off) = make_uint2(l0, l1);
    }
}
__device__ __forceinline__ float wsum(float v) {
    #pragma unroll
    for (int o = 16; o > 0; o >>= 1)
        v += __shfl_xor_sync(0xffffffffu, v, o);
    return v;
}
#endif

// ---------------------------------------------------------------------------
// ff1gw: Hf = gelu(Xin@ff1 + b1); G = gelu(Hf@wA) [TMEM only]; Wt = G@wB.
// ---------------------------------------------------------------------------
__global__ __launch_bounds__(NTH)
void ff1gw_kernel(const float* __restrict__ Xin,
                  const char* __restrict__ wF1, const float* __restrict__ bias1,
                  const char* __restrict__ wWA, const char* __restrict__ wWB,
                  float* __restrict__ Hf, float* __restrict__ Wt, int M)
{
#if TC05_OK
    extern __shared__ __align__(1024) char sm[];
    const int t = threadIdx.x, w = t >> 5, lane = t & 31;
    const int row0 = blockIdx.x * 128;
    const uint32_t sb = smem_to_u32(sm);

    if (w == 0) TCGEN05_ALLOC(sb + 0, 512);
    if (t == 0) { MBARRIER_INIT(sb + 8, 1); MBARRIER_INIT(sb + 16, 1); }
    __syncthreads();
    uint32_t tmem;
    asm volatile("ld.shared.b32 %0, [%1];" : "=r"(tmem) : "r"(sb + 0));

    // ---- stage 0: D0 (cols 0..255) = Xin @ ff1 (A software-pipelined) ----
    {
        float4 va[AITER];
        loadA4(va, Xin, row0, M, 256, 0, t);
        for (int c = 0; c < 4; ++c) {
            const int b = c & 1;
            if (c >= 2) MBARRIER_WAIT_PARITY(sb + 8 + b * 8, 0);
            fillB_async(sb + BOFF(b), wF1 + (size_t)c * 65536, 65536, t, NTH);
            storeA4<false>(sm + AOFF(b), va, t);
            if (c < 3) loadA4(va, Xin, row0, M, 256, (c + 1) * 64, t);
            CP_WAIT();
            FENCE_ASYNC();
            __syncthreads();
            if (t < 32 && elect_one_pred()) {
                mma_chunk(tmem, sb + AOFF(b), sb + BOFF(b), 16384, 32768, IDESC(256), c == 0);
                TCGEN05_COMMIT(sb + 8 + b * 8);
            }
        }
    }
    MBARRIER_WAIT_PARITY(sb + 8, 1);
    MBARRIER_WAIT_PARITY(sb + 16, 1);
    TCGEN05_FENCE_AFTER();

    // ---- stage 1: D1 (cols 256..511) = gelu(D0 + b1) @ wA ; write Hf ----
    {
        const int grow = row0 + (w & 3) * 32 + lane;
        float* HfRow = (grow < M) ? &Hf[(size_t)grow * 256] : nullptr;
        for (int c = 0; c < 4; ++c) {
            const int b = c & 1;
            uint32_t dr[8];
            TCGEN05_LD_X8(dr, tmem + c * 64 + (w >> 2) * 8);
            TCGEN05_WAIT_LD();
            if (c >= 2) MBARRIER_WAIT_PARITY(sb + 8 + b * 8, 0);
            fillB_async(sb + BOFF(b), wWA + (size_t)c * 65536, 65536, t, NTH);
            TCGEN05_FENCE_BEFORE();
            epiA8(sm + AOFF(b), dr, w, lane, bias1, c * 64, HfRow);
            CP_WAIT();
            FENCE_ASYNC();
            __syncthreads();
            if (t < 32 && elect_one_pred()) {
                mma_chunk(tmem + 256, sb + AOFF(b), sb + BOFF(b), 16384, 32768, IDESC(256), c == 0);
                TCGEN05_COMMIT(sb + 8 + b * 8);
            }
        }
    }
    MBARRIER_WAIT_PARITY(sb + 8, 1);
    MBARRIER_WAIT_PARITY(sb + 16, 1);
    TCGEN05_FENCE_AFTER();

    // ---- stage 2: D0 (cols 0..63) = gelu(D1) @ wB ----
    for (int c = 0; c < 4; ++c) {
        const int b = c & 1;
        uint32_t dr[8];
        TCGEN05_LD_X8(dr, tmem + 256 + c * 64 + (w >> 2) * 8);
        TCGEN05_WAIT_LD();
        if (c >= 2) MBARRIER_WAIT_PARITY(sb + 8 + b * 8, 0);
        fillB_async(sb + BOFF(b), wWB + (size_t)c * 16384, 16384, t, NTH);
        TCGEN05_FENCE_BEFORE();
        epiA8(sm + AOFF(b), dr, w, lane, nullptr, 0, nullptr);
        CP_WAIT();
        FENCE_ASYNC();
        __syncthreads();
        if (t < 32 && elect_one_pred()) {
            mma_chunk(tmem, sb + AOFF(b), sb + BOFF(b), 16384, 8192, IDESC(64), c == 0);
            TCGEN05_COMMIT(sb + 8 + b * 8);
        }
    }
    MBARRIER_WAIT_PARITY(sb + 8, 1);
    MBARRIER_WAIT_PARITY(sb + 16, 1);
    TCGEN05_FENCE_AFTER();

    // ---- epilogue: Wt fp32 from D0 cols 0..63 ----
    {
        int j = w >> 2;
        if (j < 2) {
            uint32_t dr[32];
            TCGEN05_LD_X32(dr, tmem + j * 32);
            TCGEN05_WAIT_LD();
            const int row = row0 + (w & 3) * 32 + lane;
            if (row < M) {
                #pragma unroll
                for (int c4 = 0; c4 < 8; c4++)
                    *reinterpret_cast<float4*>(&Wt[(size_t)row * 64 + j * 32 + c4 * 4]) =
                        make_float4(__uint_as_float(dr[c4*4]),   __uint_as_float(dr[c4*4+1]),
                                    __uint_as_float(dr[c4*4+2]), __uint_as_float(dr[c4*4+3]));
            }
        }
    }
    __syncthreads();
    if (w == 0) TCGEN05_DEALLOC(tmem, 512);
#else
    __shared__ float hrow[256], grow2[256];
    const int row0 = blockIdx.x * 128;
    const int t = threadIdx.x;
    for (int r = 0; r < 128; r++) {
        int gr = row0 + r;
        if (gr >= M) break;
        for (int h = t; h < 256; h += NTH) {
            float acc = bias1[h];
            for (int k = 0; k < 256; k++)
                acc = fmaf(Xin[(size_t)gr*256+k], wval(wF1, 256, h, k), acc);
            float f = gelu_f(acc);
            hrow[h] = f;
            Hf[(size_t)gr*256+h] = f;
        }
        __syncthreads();
        for (int h = t; h < 256; h += NTH) {
            float acc = 0.0f;
            for (int k = 0; k < 256; k++)
                acc = fmaf(hrow[k], wval(wWA, 256, h, k), acc);
            grow2[h] = gelu_f(acc);
        }
        __syncthreads();
        for (int n = t; n < 64; n += NTH) {
            float acc = 0.0f;
            for (int k = 0; k < 256; k++)
                acc = fmaf(grow2[k], wval(wWB, 64, n, k), acc);
            Wt[(size_t)gr*64+n] = acc;
        }
        __syncthreads();
    }
#endif
}

// ---------------------------------------------------------------------------
// PF: P = gelu(Wt @ Sg^T) in TMEM; X = P@ff2_top + gelu(Hf)@ff2_bot + b2.
// LAST: skip X store, emit per-CTA column sums into mp instead.
// ---------------------------------------------------------------------------
template<bool LAST>
__global__ __launch_bounds__(NTH)
void gemmPF_kernel(const float* __restrict__ Wt, const char* __restrict__ sg,
                   const float* __restrict__ Hf, const char* __restrict__ wFF2,
                   const float* __restrict__ bias2, float* __restrict__ X,
                   float* __restrict__ mp, int M)
{
#if TC05_OK
    extern __shared__ __align__(1024) char sm[];
    const int t = threadIdx.x, w = t >> 5, lane = t & 31;
    const int row0 = blockIdx.x * 128;
    const uint32_t sb = smem_to_u32(sm);

    if (w == 0) TCGEN05_ALLOC(sb + 0, 512);
    if (t == 0) { MBARRIER_INIT(sb + 8, 1); MBARRIER_INIT(sb + 16, 1); }
    __syncthreads();
    uint32_t tmem;
    asm volatile("ld.shared.b32 %0, [%1];" : "=r"(tmem) : "r"(sb + 0));
    const uint32_t idesc = IDESC(256);

    // stage 1: D0 (cols 0..255) = Wt @ Sg^T (K=64, one chunk)
    {
        fillB_async(sb + AOFF(1), sg, 65536, t, NTH);   // B tile at AOFF(1)
        float4 va[AITER];
        loadA4(va, Wt, row0, M, 64, 0, t);
        storeA4<false>(sm + AOFF(0), va, t);
        CP_WAIT();
        FENCE_ASYNC();
        __syncthreads();
        if (t < 32 && elect_one_pred()) {
            mma_chunk(tmem, sb + AOFF(0), sb + AOFF(1), 16384, 32768, idesc, true);
            TCGEN05_COMMIT(sb + 8);
        }
    }
    MBARRIER_WAIT_PARITY(sb + 8, 0);
    TCGEN05_FENCE_AFTER();
    __syncthreads();

    // stage 2: D1 (cols 256..511) = [gelu(D0) | gelu(Hf)] @ ff2  (8 chunks)
    #pragma unroll 1
    for (int c = 0; c < 8; ++c) {
        const int b = c & 1;
        uint32_t dr[8];
        float4 va[AITER];
        if (c < 4) {
            TCGEN05_LD_X8(dr, tmem + c * 64 + (w >> 2) * 8);
            TCGEN05_WAIT_LD();
        } else {
            loadA4(va, Hf, row0, M, 256, (c - 4) * 64, t);
        }
        if (c >= 2) MBARRIER_WAIT_PARITY(sb + 8 + b * 8, ((c >> 1) + (c & 1)) & 1);
        fillB_async(sb + BOFF(b), wFF2 + (size_t)c * 65536, 65536, t, NTH);
        char* aB = sm + AOFF(b);
        if (c < 4) {
            TCGEN05_FENCE_BEFORE();
            epiA8(aB, dr, w, lane, nullptr, 0, nullptr);
        } else {
            storeA4<true>(aB, va, t);
        }
        CP_WAIT();
        FENCE_ASYNC();
        __syncthreads();
        if (t < 32 && elect_one_pred()) {
            mma_chunk(tmem + 256, sb + AOFF(b), sb + BOFF(b), 16384, 32768, idesc, c == 0);
            TCGEN05_COMMIT(sb + 8 + b * 8);
        }
    }
    MBARRIER_WAIT_PARITY(sb + 8, 0);
    MBARRIER_WAIT_PARITY(sb + 16, 1);
    TCGEN05_FENCE_AFTER();

    // epilogue: X store (or per-CTA mean partials when LAST); 32 warps, one pass
    float* mp_s = reinterpret_cast<float*>(sm + 1024);   // [4][256], pipeline done
    const int row = row0 + (w & 3) * 32 + lane;
    {
        const int j = w >> 2;            // 0..7
        uint32_t dr[32];
        TCGEN05_LD_X32(dr, tmem + 256 + j * 32);
        TCGEN05_WAIT_LD();
        #pragma unroll
        for (int c4 = 0; c4 < 8; c4++) {
            float4 v;
            v.x = __uint_as_float(dr[c4*4])   + bias2[j*32 + c4*4];
            v.y = __uint_as_float(dr[c4*4+1]) + bias2[j*32 + c4*4+1];
            v.z = __uint_as_float(dr[c4*4+2]) + bias2[j*32 + c4*4+2];
            v.w = __uint_as_float(dr[c4*4+3]) + bias2[j*32 + c4*4+3];
            if (!LAST) {
                if (row < M)
                    *reinterpret_cast<float4*>(&X[(size_t)row * 256 + j * 32 + c4 * 4]) = v;
            } else {
                if (row >= M) { v.x = v.y = v.z = v.w = 0.f; }
                v.x = wsum(v.x); v.y = wsum(v.y); v.z = wsum(v.z); v.w = wsum(v.w);
                if (lane == 0)
                    *reinterpret_cast<float4*>(&mp_s[(w & 3) * 256 + j * 32 + c4 * 4]) = v;
            }
        }
    }
    if (LAST) {
        __syncthreads();
        if (t < 256)
            mp[(size_t)blockIdx.x * 256 + t] =
                mp_s[t] + mp_s[256 + t] + mp_s[512 + t] + mp_s[768 + t];
    }
    __syncthreads();
    if (w == 0) TCGEN05_DEALLOC(tmem, 512);
#else
    __shared__ float prow[256];
    __shared__ float msum[256];
    const int row0 = blockIdx.x * 128;
    const int t = threadIdx.x;
    if (LAST) { if (t < 256) msum[t] = 0.f; __syncthreads(); }
    for (int r = 0; r < 128; r++) {
        int gr = row0 + r;
        if (gr >= M) break;
        for (int n = t; n < 256; n += NTH) {
            float acc = 0.0f;
            for (int k = 0; k < 64; k++)
                acc = fmaf(Wt[(size_t)gr*64+k], wval(sg, 256, n, k), acc);
            prow[n] = gelu_f(acc);
        }
        __syncthreads();
        for (int n = t; n < 256; n += NTH) {
            float acc = bias2[n];
            for (int k = 0; k < 256; k++)
                acc = fmaf(prow[k], wval(wFF2, 256, n, k), acc);
            for (int k = 0; k < 256; k++)
                acc = fmaf(gelu_f(Hf[(size_t)gr*256+k]), wval(wFF2, 256, n, 256 + k), acc);
            if (!LAST) X[(size_t)gr*256+n] = acc;
            else       msum[n] += acc;
        }
        __syncthreads();
    }
    if (LAST && t < 256) mp[(size_t)blockIdx.x * 256 + t] = msum[t];
#endif
}

// ---------------------------------------------------------------------------
// spartial05: S partials via tcgen05 (1024 threads).
// ---------------------------------------------------------------------------
__global__ __launch_bounds__(NTH)
void spartial05_kernel(const float* __restrict__ Hf, const float* __restrict__ Wt,
                       float* __restrict__ part, int N)
{
#if TC05_OK
    extern __shared__ __align__(1024) char sm[];
    const int t = threadIdx.x, w = t >> 5, lane = t & 31;
    const uint32_t sb = smem_to_u32(sm);
    const int totalChunks = (N + 63) >> 6;
    const int per = (totalChunks + SPGRID - 1) / SPGRID;
    const int cbeg = blockIdx.x * per;
    const int cend = min(totalChunks, cbeg + per);
    const int nch = cend - cbeg;
    float* myPart = part + (size_t)blockIdx.x * HDIM * MDIM;

    if (w == 0) TCGEN05_ALLOC(sb + 0, 128);
    if (t == 0) { MBARRIER_INIT(sb + 8, 1); MBARRIER_INIT(sb + 16, 1); }
    __syncthreads();
    uint32_t tmem;
    asm volatile("ld.shared.b32 %0, [%1];" : "=r"(tmem) : "r"(sb + 0));

    if (nch > 0) {
        const uint32_t idesc = IDESC(64);
        for (int ci = 0; ci < nch; ++ci) {
            const int b = ci & 1;
            if ((ci >> 1) >= 1) MBARRIER_WAIT_PARITY(sb + 8 + b * 8, ((ci >> 1) - 1) & 1);
            char* buf = sm + 1024 + b * 81920;
            const int rbeg = (cbeg + ci) * 64;

            #pragma unroll
            for (int i = 0; i < 2048 / NTH; i++) {
                int fid = t + i * NTH;
                int kp = fid & 31, hg = fid >> 5;
                int h0 = hg * 4;
                int k0 = rbeg + 2 * kp;
                float4 fa = (k0     < N) ? *reinterpret_cast<const float4*>(&Hf[(size_t)k0 * 256 + h0])
                                         : make_float4(0.f, 0.f, 0.f, 0.f);
                float4 fb = (k0 + 1 < N) ? *reinterpret_cast<const float4*>(&Hf[(size_t)(k0 + 1) * 256 + h0])
                                         : make_float4(0.f, 0.f, 0.f, 0.f);
                char* ah = buf + (h0 >> 7) * 32768;
                int r0 = h0 & 127;
                const float* pa = &fa.x;
                const float* pb = &fb.x;
                #pragma unroll
                for (int j = 0; j < 4; j++) {
                    uint32_t hp, lp;
                    split2(pa[j], pb[j], hp, lp);
                    int off = SWZ((r0 + j) * 128 + kp * 4);
                    *reinterpret_cast<uint32_t*>(ah + off)         = hp;
                    *reinterpret_cast<uint32_t*>(ah + 16384 + off) = lp;
                }
            }
            if (t < 512) {
                int kp = t & 31, mg = t >> 5;
                int m0 = mg * 4;
                int k0 = rbeg + 2 * kp;
                float4 fa = (k0     < N) ? *reinterpret_cast<const float4*>(&Wt[(size_t)k0 * 64 + m0])
                                         : make_float4(0.f, 0.f, 0.f, 0.f);
                float4 fb = (k0 + 1 < N) ? *reinterpret_cast<const float4*>(&Wt[(size_t)(k0 + 1) * 64 + m0])
                                         : make_float4(0.f, 0.f, 0.f, 0.f);
                char* bh = buf + 65536;
                const float* pa = &fa.x;
                const float* pb = &fb.x;
                #pragma unroll
                for (int j = 0; j < 4; j++) {
                    uint32_t hp, lp;
                    split2(pa[j], pb[j], hp, lp);
                    int off = SWZ((m0 + j) * 128 + kp * 4);
                    *reinterpret_cast<uint32_t*>(bh + off)        = hp;
                    *reinterpret_cast<uint32_t*>(bh + 8192 + off) = lp;
                }
            }
            FENCE_ASYNC();
            __syncthreads();
            if (t < 32 && elect_one_pred()) {
                uint32_t aBase = sb + 1024 + b * 81920;
                mma_chunk(tmem,      aBase,         aBase + 65536, 16384, 8192, idesc, ci == 0);
                mma_chunk(tmem + 64, aBase + 32768, aBase + 65536, 16384, 8192, idesc, ci == 0);
                TCGEN05_COMMIT(sb + 8 + b * 8);
            }
        }
        MBARRIER_WAIT_PARITY(sb + 8 + ((nch - 1) & 1) * 8, ((nch - 1) >> 1) & 1);
        TCGEN05_FENCE_AFTER();

        {
            int idx = w >> 2;
            if (idx < 4) {
                int mt = idx >> 1, s = idx & 1;
                uint32_t dr[32];
                TCGEN05_LD_X32(dr, tmem + mt * 64 + s * 32);
                TCGEN05_WAIT_LD();
                int h = mt * 128 + (w & 3) * 32 + lane;
                float* p = myPart + (size_t)h * 64 + s * 32;
                #pragma unroll
                for (int c4 = 0; c4 < 8; c4++)
                    *reinterpret_cast<float4*>(&p[c4 * 4]) =
                        make_float4(__uint_as_float(dr[c4*4]),   __uint_as_float(dr[c4*4+1]),
                                    __uint_as_float(dr[c4*4+2]), __uint_as_float(dr[c4*4+3]));
            }
        }
    } else {
        for (int i = t; i < HDIM * MDIM; i += NTH)
            myPart[i] = 0.0f;
    }
    __syncthreads();
    if (w == 0) TCGEN05_DEALLOC(tmem, 128);
#else
    const int t = threadIdx.x;
    const int hq = t & 127, mq = (t >> 7) & 3;
    const int totalChunks = (N + 63) >> 6;
    const int per = (totalChunks + SPGRID - 1) / SPGRID;
    const int rbeg = blockIdx.x * per * 64;
    const int rend = min(N, (blockIdx.x + 1) * per * 64);
    const int half = t >> 9;             // 0/1: split rows among thread halves
    float acc[2][16];
    #pragma unroll
    for (int j = 0; j < 2; j++)
        #pragma unroll
        for (int i = 0; i < 16; i++) acc[j][i] = 0.0f;
    for (int r = rbeg + half; r < rend; r += 2) {
        float a0 = Hf[(size_t)r * HDIM + hq * 2];
        float a1 = Hf[(size_t)r * HDIM + hq * 2 + 1];
        #pragma unroll
        for (int i = 0; i < 16; i++) {
            float wv = Wt[(size_t)r * MDIM + mq * 16 + i];
            acc[0][i] = fmaf(a0, wv, acc[0][i]);
            acc[1][i] = fmaf(a1, wv, acc[1][i]);
        }
    }
    __shared__ float red[2][16];   // tiny serialization-safe reduce via atomics-free two-pass
    // simple: thread half 1 adds into smem staging then half 0 accumulates
    __shared__ float stage[512 * 2]; // unused fallback simplification
    (void)red; (void)stage;
    // For fallback correctness with 1024 threads, recompute serially by half 0 only:
    if (half == 0) {
        float accF[2][16];
        #pragma unroll
        for (int j = 0; j < 2; j++)
            #pragma unroll
            for (int i = 0; i < 16; i++) accF[j][i] = 0.0f;
        for (int r = rbeg; r < rend; r++) {
            float a0 = Hf[(size_t)r * HDIM + hq * 2];
            float a1 = Hf[(size_t)r * HDIM + hq * 2 + 1];
            #pragma unroll
            for (int i = 0; i < 16; i++) {
                float wv = Wt[(size_t)r * MDIM + mq * 16 + i];
                accF[0][i] = fmaf(a0, wv, accF[0][i]);
                accF[1][i] = fmaf(a1, wv, accF[1][i]);
            }
        }
        float* myPart = part + (size_t)blockIdx.x * HDIM * MDIM;
        #pragma unroll
        for (int j = 0; j < 2; j++)
            #pragma unroll
            for (int i = 0; i < 16; i++)
                myPart[(size_t)(hq * 2 + j) * MDIM + mq * 16 + i] = accF[j][i];
    }
#endif
}

// Sum SPGRID partials, gelu, emit Sg^T pre-swizzled tile.
__global__ __launch_bounds__(256)
void sfinal_kernel(const float* __restrict__ part, char* __restrict__ sg)
{
    int idx = blockIdx.x * 256 + threadIdx.x;   // h*64+m
    float s = 0.0f;
    for (int p = 0; p < SPGRID; p++)
        s += part[(size_t)p * HDIM * MDIM + idx];
    float g = gelu_f(s);
    __nv_bfloat16 h = __float2bfloat16_rn(g);
    __nv_bfloat16 l = __float2bfloat16_rn(g - __bfloat162float(h));
    int hh = idx >> 6, m = idx & 63;
    uint32_t so = SWZ(hh * 128 + m * 2);
    *reinterpret_cast<__nv_bfloat16*>(sg + so)         = h;
    *reinterpret_cast<__nv_bfloat16*>(sg + 32768 + so) = l;
}

// weight prep: single launch, chunked swizzled tile layout
__constant__ int c_wOff[9] = {0, 65536, 131072, 147456, 278528, 344064, 409600, 425984, 557056};
__constant__ int c_wK[8]   = {256, 256, 256, 512, 256, 256, 256, 512};
__constant__ int c_wNc[8]  = {256, 256, 64, 256, 256, 256, 64, 256};
__constant__ int c_wB[8]   = {0, 262144, 524288, 589824, 1114112, 1376256, 1638400, 1703936};
__global__ void transsplit_all(const float* s0, const float* s1, const float* s2, const float* s3,
                               const float* s4, const float* s5, const float* s6, const float* s7,
                               char* __restrict__ wsw)
{
    int idx = blockIdx.x * 256 + threadIdx.x;
    if (idx >= 557056) return;
    int i = 0;
    while (idx >= c_wOff[i + 1]) i++;
    const float* srcs[8] = {s0, s1, s2, s3, s4, s5, s6, s7};
    int local = idx - c_wOff[i];
    int K = c_wK[i], Nc = c_wNc[i];
    int n = local / K, k = local % K;
    float v = srcs[i][(size_t)k * Nc + n];
    __nv_bfloat16 h = __float2bfloat16_rn(v);
    __nv_bfloat16 l = __float2bfloat16_rn(v - __bfloat162float(h));
    int ch = k >> 6, kk = k & 63;
    char* base = wsw + c_wB[i] + (size_t)ch * (Nc * 256);
    uint32_t so = SWZ(n * 128 + kk * 2);
    *reinterpret_cast<__nv_bfloat16*>(base + so)            = h;
    *reinterpret_cast<__nv_bfloat16*>(base + Nc * 128 + so) = l;
}

// head: out = (sum of per-CTA partials / N) @ head_w + head_b
__global__ __launch_bounds__(256)
void head_kernel(const float* __restrict__ part, const float* __restrict__ hw,
                 const float* __restrict__ hb, float* __restrict__ out,
                 int N, int gridN)
{
    __shared__ float s[HDIM];
    int t = threadIdx.x;
    float a = 0.0f;
    for (int p = 0; p < gridN; p++) a += part[(size_t)p * HDIM + t];
    s[t] = a * (1.0f / (float)N);
    __syncthreads();
    if (t < 64) {
        float o = hb[t];
        #pragma unroll 8
        for (int h = 0; h < HDIM; h++)
            o = fmaf(s[h], hw[h * 64 + t], o);
        out[t] = o;
    }
}

// ---------------------------------------------------------------------------
// Host
// ---------------------------------------------------------------------------
extern "C" void kernel_launch(void* const* d_in, const int* in_sizes, int n_in,
                              void* d_out, int out_size)
{
    const float* x      = (const float*)d_in[0];
    const float* ff1_w0 = (const float*)d_in[2];
    const float* ff1_b0 = (const float*)d_in[3];
    const float* wA0    = (const float*)d_in[4];
    const float* wB0    = (const float*)d_in[5];
    const float* ff2_w0 = (const float*)d_in[6];
    const float* ff2_b0 = (const float*)d_in[7];
    const float* ff1_w1 = (const float*)d_in[8];
    const float* ff1_b1 = (const float*)d_in[9];
    const float* wA1    = (const float*)d_in[10];
    const float* wB1    = (const float*)d_in[11];
    const float* ff2_w1 = (const float*)d_in[12];
    const float* ff2_b1 = (const float*)d_in[13];
    const float* head_w = (const float*)d_in[14];
    const float* head_b = (const float*)d_in[15];
    float* out = (float*)d_out;

    const int N = in_sizes[0] / HDIM;
    const int grid = (N + 127) / 128;

    float *pHf, *pX, *pWt, *pPart, *pMp;
    char *pWsw, *pSg;
    cudaGetSymbolAddress((void**)&pHf,   g_Hf);
    cudaGetSymbolAddress((void**)&pX,    g_X);
    cudaGetSymbolAddress((void**)&pWt,   g_Wt);
    cudaGetSymbolAddress((void**)&pPart, g_part);
    cudaGetSymbolAddress((void**)&pMp,   g_mp);
    cudaGetSymbolAddress((void**)&pWsw,  g_wsw);
    cudaGetSymbolAddress((void**)&pSg,   g_sgsw);

    cudaFuncSetAttribute(ff1gw_kernel,         cudaFuncAttributeMaxDynamicSharedMemorySize, FSMEM);
    cudaFuncSetAttribute(gemmPF_kernel<false>, cudaFuncAttributeMaxDynamicSharedMemorySize, FSMEM);
    cudaFuncSetAttribute(gemmPF_kernel<true>,  cudaFuncAttributeMaxDynamicSharedMemorySize, FSMEM);
    cudaFuncSetAttribute(spartial05_kernel,    cudaFuncAttributeMaxDynamicSharedMemorySize, SPSMEM);

    transsplit_all<<<(557056 + 255) / 256, 256>>>(ff1_w0, wA0, wB0, ff2_w0,
                                                  ff1_w1, wA1, wB1, ff2_w1, pWsw);

    const float* Xin = x;
    const float* ff1b[2] = {ff1_b0, ff1_b1};
    const float* ff2b[2] = {ff2_b0, ff2_b1};
    for (int b = 0; b < 2; b++) {
        size_t wo = (size_t)b * WB_BLK;
        ff1gw_kernel<<<grid, NTH, FSMEM>>>(Xin,
            pWsw + wo + WB_FF1, ff1b[b],
            pWsw + wo + WB_WA, pWsw + wo + WB_WB, pHf, pWt, N);
        spartial05_kernel<<<SPGRID, NTH, SPSMEM>>>(pHf, pWt, pPart, N);
        sfinal_kernel<<<64, 256>>>(pPart, pSg);
        if (b == 0)
            gemmPF_kernel<false><<<grid, NTH, FSMEM>>>(pWt, pSg, pHf,
                pWsw + wo + WB_FF2, ff2b[b], pX, pMp, N);
        else
            gemmPF_kernel<true><<<grid, NTH, FSMEM>>>(pWt, pSg, pHf,
                pWsw + wo + WB_FF2, ff2b[b], pX, pMp, N);
        Xin = pX;
    }

    head_kernel<<<1, 256>>>(pMp, head_w, head_b, out, N, grid);
}

// round 15
// speedup vs baseline: 1.0316x; 1.0316x over previous
#include <cuda_runtime.h>
#include <cuda_bf16.h>
#include <cstdint>
#include <cstddef>

// ---------------------------------------------------------------------------
// GHM — tcgen05 pipeline v12: v11 + cp.async.bulk (complete_tx mbarrier)
// weight fills — one bulk op replaces 8192 cp.async issues per chunk.
// ---------------------------------------------------------------------------

#if defined(__CUDA_ARCH_FEAT_SM103_ALL) || defined(__CUDA_ARCH_FEAT_SM100_ALL)
#define TC05_OK 1
#else
#define TC05_OK 0
#endif

#define NMAX 200000
#define HDIM 256
#define MDIM 64
#define NTH  1024
#define AITER (2048 / NTH)
#define SPGRID 148
#define MAXCTA 1600

__device__ float g_Hf [(size_t)NMAX * HDIM];
__device__ float g_X  [(size_t)NMAX * HDIM];
__device__ float g_Wt [(size_t)NMAX * MDIM];
__device__ float g_part[(size_t)SPGRID * HDIM * MDIM];
__device__ float g_mp [(size_t)MAXCTA * HDIM];
#define WB_FF1 0
#define WB_WA  262144
#define WB_WB  524288
#define WB_FF2 589824
#define WB_BLK 1114112
__device__ __align__(16) char g_wsw[2 * WB_BLK];
__device__ __align__(16) char g_sgsw[65536];     // Sg^T tile, Nc=256, K=64

__device__ __forceinline__ float gelu_f(float x) {
    return 0.5f * x * (1.0f + erff(x * 0.70710678118654752440f));
}
__device__ __forceinline__ uint32_t packbf(float lo, float hi) {
    uint32_t r;
    asm("cvt.rn.bf16x2.f32 %0, %1, %2;" : "=r"(r) : "f"(hi), "f"(lo));
    return r;
}
__device__ __forceinline__ void split2(float f0, float f1, uint32_t& h, uint32_t& l) {
    h = packbf(f0, f1);
    float fx = __uint_as_float(h << 16), fy = __uint_as_float(h & 0xffff0000u);
    l = packbf(f0 - fx, f1 - fy);
}

#define SWZ(b) ((b) ^ (((b) >> 3) & 0x70))

// fallback-only weight reconstruct
__device__ __forceinline__ float wval(const char* w, int Nc, int n, int k) {
    int ch = k >> 6, kk = k & 63;
    const char* base = w + (size_t)ch * Nc * 256;
    uint32_t so = SWZ(n * 128 + kk * 2);
    return __bfloat162float(*(const __nv_bfloat16*)(base + so)) +
           __bfloat162float(*(const __nv_bfloat16*)(base + Nc * 128 + so));
}

#if TC05_OK
__device__ __forceinline__ uint32_t elect_one_pred() {
    uint32_t pred;
    asm volatile("{\n\t.reg .pred p;\n\telect.sync _|p, 0xFFFFFFFF;\n\t"
                 "selp.b32 %0, 1, 0, p;\n\t}" : "=r"(pred));
    return pred;
}
__device__ __forceinline__ uint32_t smem_to_u32(const void* p) {
    uint32_t a;
    asm("{ .reg .u64 t; cvta.to.shared.u64 t, %1; cvt.u32.u64 %0, t; }"
        : "=r"(a) : "l"(p));
    return a;
}
#define TCGEN05_ALLOC(sa, n) \
    asm volatile("tcgen05.alloc.cta_group::1.sync.aligned.shared::cta.b32 [%0], %1;" \
                 :: "r"((uint32_t)(sa)), "r"((uint32_t)(n)) : "memory")
#define TCGEN05_DEALLOC(ta, n) \
    asm volatile("tcgen05.dealloc.cta_group::1.sync.aligned.b32 %0, %1;" \
                 :: "r"(ta), "r"((uint32_t)(n)))
#define TCGEN05_COMMIT(mb) \
    asm volatile("tcgen05.commit.cta_group::1.mbarrier::arrive::one.shared::cluster.b64 [%0];" \
                 :: "r"((uint32_t)(mb)) : "memory")
#define TCGEN05_WAIT_LD()  asm volatile("tcgen05.wait::ld.sync.aligned;" ::: "memory")
#define TCGEN05_FENCE_AFTER()  asm volatile("tcgen05.fence::after_thread_sync;" ::: "memory")
#define TCGEN05_FENCE_BEFORE() asm volatile("tcgen05.fence::before_thread_sync;" ::: "memory")
#define FENCE_ASYNC() asm volatile("fence.proxy.async.shared::cta;" ::: "memory")
#define MBARRIER_INIT(mb, c) \
    asm volatile("mbarrier.init.shared.b64 [%0], %1;" :: "r"((uint32_t)(mb)), "r"((uint32_t)(c)) : "memory")
#define MBAR_EXPECT_TX(mb, bytes) \
    asm volatile("mbarrier.arrive.expect_tx.shared.b64 _, [%0], %1;" \
                 :: "r"((uint32_t)(mb)), "r"((uint32_t)(bytes)) : "memory")
#define BULK_G2S(dst, src, bytes, mb) \
    asm volatile("cp.async.bulk.shared::cta.global.mbarrier::complete_tx::bytes [%0], [%1], %2, [%3];" \
                 :: "r"((uint32_t)(dst)), "l"(src), "r"((uint32_t)(bytes)), "r"((uint32_t)(mb)) : "memory")
#define MBARRIER_WAIT_PARITY(mb, ph) do { \
    uint32_t _m = (uint32_t)(mb), _p = (uint32_t)(ph), _d; \
    asm volatile("{\n\t.reg .pred p;\n\t" \
        "mbarrier.try_wait.parity.acquire.cta.shared::cta.b64 p, [%1], %2;\n\t" \
        "selp.b32 %0, 1, 0, p;\n\t}" : "=r"(_d) : "r"(_m), "r"(_p) : "memory"); \
    if (!_d) { \
        asm volatile("{\n\t.reg .pred P1;\n\tWL_%=: \n\t" \
            "mbarrier.try_wait.parity.acquire.cta.shared::cta.b64 P1, [%0], %1, 0x989680;\n\t" \
            "@P1 bra.uni WD_%=;\n\tbra.uni WL_%=;\n\tWD_%=: \n\t}" \
            :: "r"(_m), "r"(_p) : "memory"); \
    } } while (0)
#define TCGEN05_LD_X32(r, ta) \
    asm volatile("tcgen05.ld.sync.aligned.32x32b.x32.b32 " \
        "{%0,%1,%2,%3,%4,%5,%6,%7,%8,%9,%10,%11,%12,%13,%14,%15," \
        "%16,%17,%18,%19,%20,%21,%22,%23,%24,%25,%26,%27,%28,%29,%30,%31}, [%32];" \
        : "=r"((r)[0]),"=r"((r)[1]),"=r"((r)[2]),"=r"((r)[3]),"=r"((r)[4]),"=r"((r)[5]), \
          "=r"((r)[6]),"=r"((r)[7]),"=r"((r)[8]),"=r"((r)[9]),"=r"((r)[10]),"=r"((r)[11]), \
          "=r"((r)[12]),"=r"((r)[13]),"=r"((r)[14]),"=r"((r)[15]),"=r"((r)[16]),"=r"((r)[17]), \
          "=r"((r)[18]),"=r"((r)[19]),"=r"((r)[20]),"=r"((r)[21]),"=r"((r)[22]),"=r"((r)[23]), \
          "=r"((r)[24]),"=r"((r)[25]),"=r"((r)[26]),"=r"((r)[27]),"=r"((r)[28]),"=r"((r)[29]), \
          "=r"((r)[30]),"=r"((r)[31]) : "r"(ta))
#define TCGEN05_LD_X8(r, ta) \
    asm volatile("tcgen05.ld.sync.aligned.32x32b.x8.b32 " \
        "{%0,%1,%2,%3,%4,%5,%6,%7}, [%8];" \
        : "=r"((r)[0]),"=r"((r)[1]),"=r"((r)[2]),"=r"((r)[3]), \
          "=r"((r)[4]),"=r"((r)[5]),"=r"((r)[6]),"=r"((r)[7]) : "r"(ta))

static constexpr uint64_t SMEM_DESC_BASE_SW128 =
    (uint64_t(2) << 61) | (uint64_t(1) << 46) | (uint64_t(64) << 32) | (uint64_t(1) << 16);
#define MAKE_SMEM_DESC(a) (SMEM_DESC_BASE_SW128 | ((uint64_t)((a) >> 4) & 0x3FFF))

__device__ __forceinline__ void mma_f16_ss(uint32_t d, uint64_t ad, uint64_t bd,
                                           uint32_t idesc, uint32_t en) {
    asm volatile("{\n\t.reg .pred p;\n\tsetp.ne.u32 p, %5, 0;\n\t"
        "tcgen05.mma.cta_group::1.kind::f16 [%0], %1, %2, %3, {%4,%4,%4,%4}, p;\n\t}"
        :: "r"(d), "l"(ad), "l"(bd), "r"(idesc), "r"(0u), "r"(en) : "memory");
}

__device__ __forceinline__ void mma_chunk(uint32_t d, uint32_t sb_ah, uint32_t sb_bh,
                                          int aL, int bL, uint32_t idesc, bool first) {
    const uint64_t adh = MAKE_SMEM_DESC(sb_ah), adl = MAKE_SMEM_DESC(sb_ah + aL);
    const uint64_t bdh = MAKE_SMEM_DESC(sb_bh), bdl = MAKE_SMEM_DESC(sb_bh + bL);
    #pragma unroll
    for (int ks = 0; ks < 4; ks++) {
        uint64_t off = (uint64_t)(ks * 2);
        mma_f16_ss(d, adh + off, bdh + off, idesc, (first && ks == 0) ? 0u : 1u);
        mma_f16_ss(d, adh + off, bdl + off, idesc, 1u);
        mma_f16_ss(d, adl + off, bdh + off, idesc, 1u);
    }
}
#endif // TC05_OK

#define IDESC(Nc) ((1u << 4) | (1u << 7) | (1u << 10) | ((uint32_t)((Nc) / 8) << 17) | (8u << 24))
#define AOFF(b)  (1024 + (b) * 32768)
#define BOFF(b)  (66560 + (b) * 65536)
#define FSMEM    197632
#define SPSMEM   (1024 + 2 * 81920)
// smem mbar map: [8],[16] mma mbars; [24],[32] fill mbars
#define FMB(b)   (24 + (b) * 8)

#if TC05_OK
__device__ __forceinline__ void loadA4(float4* va, const float* A, int row0, int M,
                                       int strideK, int kc0, int t) {
    #pragma unroll
    for (int i = 0; i < AITER; i++) {
        int fid = t + i * NTH;
        int r = fid >> 4, c16 = fid & 15;
        int gr = row0 + r;
        va[i] = make_float4(0.f, 0.f, 0.f, 0.f);
        if (gr < M)
            va[i] = *reinterpret_cast<const float4*>(&A[(size_t)gr * strideK + kc0 + c16 * 4]);
    }
}
template<bool GELU_A>
__device__ __forceinline__ void storeA4(char* aB, const float4* va, int t) {
    #pragma unroll
    for (int i = 0; i < AITER; i++) {
        int fid = t + i * NTH;
        int r = fid >> 4, c16 = fid & 15;
        float4 v = va[i];
        if (GELU_A) { v.x = gelu_f(v.x); v.y = gelu_f(v.y); v.z = gelu_f(v.z); v.w = gelu_f(v.w); }
        uint32_t h0, l0, h1, l1;
        split2(v.x, v.y, h0, l0);
        split2(v.z, v.w, h1, l1);
        int swo = SWZ(r * 128 + c16 * 8);
        *reinterpret_cast<uint2*>(aB + swo)         = make_uint2(h0, h1);
        *reinterpret_cast<uint2*>(aB + 16384 + swo) = make_uint2(l0, l1);
    }
}
// 32-warp TMEM-sourced A-tile producer (LDTM.x8): seg = w>>2, sub = w&3.
__device__ __forceinline__ void epiA8(char* aB, const uint32_t* dr, int w, int lane,
                                      const float* bias, int colBase,
                                      float* HfRow /*or null*/) {
    const int seg = w >> 2;
    const int r = (w & 3) * 32 + lane;
    #pragma unroll
    for (int q = 0; q < 2; q++) {
        float f0 = __uint_as_float(dr[4*q]);
        float f1 = __uint_as_float(dr[4*q+1]);
        float f2 = __uint_as_float(dr[4*q+2]);
        float f3 = __uint_as_float(dr[4*q+3]);
        if (bias) {
            int col = colBase + seg * 8 + 4 * q;
            f0 += bias[col]; f1 += bias[col+1]; f2 += bias[col+2]; f3 += bias[col+3];
        }
        f0 = gelu_f(f0); f1 = gelu_f(f1); f2 = gelu_f(f2); f3 = gelu_f(f3);
        if (HfRow)
            *reinterpret_cast<float4*>(&HfRow[colBase + seg * 8 + 4 * q]) =
                make_float4(f0, f1, f2, f3);
        uint32_t h0, l0, h1, l1;
        split2(f0, f1, h0, l0);
        split2(f2, f3, h1, l1);
        int off = SWZ(r * 128 + seg * 16 + q * 8);
        *reinterpret_cast<uint2*>(aB + off)         = make_uint2(h0, h1);
        *reinterpret_cast<uint2*>(aB + 16384 + off) = make_uint2(l0, l1);
    }
}
__device__ __forceinline__ float wsum(float v) {
    #pragma unroll
    for (int o = 16; o > 0; o >>= 1)
        v += __shfl_xor_sync(0xffffffffu, v, o);
    return v;
}
#endif

// ---------------------------------------------------------------------------
// ff1gw: Hf = gelu(Xin@ff1 + b1); G = gelu(Hf@wA) [TMEM only]; Wt = G@wB.
// ---------------------------------------------------------------------------
__global__ __launch_bounds__(NTH)
void ff1gw_kernel(const float* __restrict__ Xin,
                  const char* __restrict__ wF1, const float* __restrict__ bias1,
                  const char* __restrict__ wWA, const char* __restrict__ wWB,
                  float* __restrict__ Hf, float* __restrict__ Wt, int M)
{
#if TC05_OK
    extern __shared__ __align__(1024) char sm[];
    const int t = threadIdx.x, w = t >> 5, lane = t & 31;
    const int row0 = blockIdx.x * 128;
    const uint32_t sb = smem_to_u32(sm);

    if (w == 0) TCGEN05_ALLOC(sb + 0, 512);
    if (t == 0) {
        MBARRIER_INIT(sb + 8, 1);  MBARRIER_INIT(sb + 16, 1);
        MBARRIER_INIT(sb + 24, 1); MBARRIER_INIT(sb + 32, 1);
    }
    __syncthreads();
    uint32_t tmem;
    asm volatile("ld.shared.b32 %0, [%1];" : "=r"(tmem) : "r"(sb + 0));
    int fu[2] = {0, 0};     // fill-mbar use counters (uniform across threads)

    // ---- stage 0: D0 (cols 0..255) = Xin @ ff1 (A software-pipelined) ----
    {
        float4 va[AITER];
        loadA4(va, Xin, row0, M, 256, 0, t);
        for (int c = 0; c < 4; ++c) {
            const int b = c & 1;
            if (c >= 2) MBARRIER_WAIT_PARITY(sb + 8 + b * 8, 0);
            if (t < 32 && elect_one_pred()) {
                MBAR_EXPECT_TX(sb + FMB(b), 65536);
                BULK_G2S(sb + BOFF(b), wF1 + (size_t)c * 65536, 65536, sb + FMB(b));
            }
            storeA4<false>(sm + AOFF(b), va, t);
            if (c < 3) loadA4(va, Xin, row0, M, 256, (c + 1) * 64, t);
            FENCE_ASYNC();
            __syncthreads();
            if (t < 32 && elect_one_pred()) {
                MBARRIER_WAIT_PARITY(sb + FMB(b), fu[b] & 1);
                mma_chunk(tmem, sb + AOFF(b), sb + BOFF(b), 16384, 32768, IDESC(256), c == 0);
                TCGEN05_COMMIT(sb + 8 + b * 8);
            }
            fu[b]++;
        }
    }
    MBARRIER_WAIT_PARITY(sb + 8, 1);
    MBARRIER_WAIT_PARITY(sb + 16, 1);
    TCGEN05_FENCE_AFTER();

    // ---- stage 1: D1 (cols 256..511) = gelu(D0 + b1) @ wA ; write Hf ----
    {
        const int grow = row0 + (w & 3) * 32 + lane;
        float* HfRow = (grow < M) ? &Hf[(size_t)grow * 256] : nullptr;
        for (int c = 0; c < 4; ++c) {
            const int b = c & 1;
            uint32_t dr[8];
            TCGEN05_LD_X8(dr, tmem + c * 64 + (w >> 2) * 8);
            TCGEN05_WAIT_LD();
            if (c >= 2) MBARRIER_WAIT_PARITY(sb + 8 + b * 8, 0);
            if (t < 32 && elect_one_pred()) {
                MBAR_EXPECT_TX(sb + FMB(b), 65536);
                BULK_G2S(sb + BOFF(b), wWA + (size_t)c * 65536, 65536, sb + FMB(b));
            }
            TCGEN05_FENCE_BEFORE();
            epiA8(sm + AOFF(b), dr, w, lane, bias1, c * 64, HfRow);
            FENCE_ASYNC();
            __syncthreads();
            if (t < 32 && elect_one_pred()) {
                MBARRIER_WAIT_PARITY(sb + FMB(b), fu[b] & 1);
                mma_chunk(tmem + 256, sb + AOFF(b), sb + BOFF(b), 16384, 32768, IDESC(256), c == 0);
                TCGEN05_COMMIT(sb + 8 + b * 8);
            }
            fu[b]++;
        }
    }
    MBARRIER_WAIT_PARITY(sb + 8, 1);
    MBARRIER_WAIT_PARITY(sb + 16, 1);
    TCGEN05_FENCE_AFTER();

    // ---- stage 2: D0 (cols 0..63) = gelu(D1) @ wB ----
    for (int c = 0; c < 4; ++c) {
        const int b = c & 1;
        uint32_t dr[8];
        TCGEN05_LD_X8(dr, tmem + 256 + c * 64 + (w >> 2) * 8);
        TCGEN05_WAIT_LD();
        if (c >= 2) MBARRIER_WAIT_PARITY(sb + 8 + b * 8, 0);
        if (t < 32 && elect_one_pred()) {
            MBAR_EXPECT_TX(sb + FMB(b), 16384);
            BULK_G2S(sb + BOFF(b), wWB + (size_t)c * 16384, 16384, sb + FMB(b));
        }
        TCGEN05_FENCE_BEFORE();
        epiA8(sm + AOFF(b), dr, w, lane, nullptr, 0, nullptr);
        FENCE_ASYNC();
        __syncthreads();
        if (t < 32 && elect_one_pred()) {
            MBARRIER_WAIT_PARITY(sb + FMB(b), fu[b] & 1);
            mma_chunk(tmem, sb + AOFF(b), sb + BOFF(b), 16384, 8192, IDESC(64), c == 0);
            TCGEN05_COMMIT(sb + 8 + b * 8);
        }
        fu[b]++;
    }
    MBARRIER_WAIT_PARITY(sb + 8, 1);
    MBARRIER_WAIT_PARITY(sb + 16, 1);
    TCGEN05_FENCE_AFTER();

    // ---- epilogue: Wt fp32 from D0 cols 0..63 ----
    {
        int j = w >> 2;
        if (j < 2) {
            uint32_t dr[32];
            TCGEN05_LD_X32(dr, tmem + j * 32);
            TCGEN05_WAIT_LD();
            const int row = row0 + (w & 3) * 32 + lane;
            if (row < M) {
                #pragma unroll
                for (int c4 = 0; c4 < 8; c4++)
                    *reinterpret_cast<float4*>(&Wt[(size_t)row * 64 + j * 32 + c4 * 4]) =
                        make_float4(__uint_as_float(dr[c4*4]),   __uint_as_float(dr[c4*4+1]),
                                    __uint_as_float(dr[c4*4+2]), __uint_as_float(dr[c4*4+3]));
            }
        }
    }
    __syncthreads();
    if (w == 0) TCGEN05_DEALLOC(tmem, 512);
#else
    __shared__ float hrow[256], grow2[256];
    const int row0 = blockIdx.x * 128;
    const int t = threadIdx.x;
    for (int r = 0; r < 128; r++) {
        int gr = row0 + r;
        if (gr >= M) break;
        for (int h = t; h < 256; h += NTH) {
            float acc = bias1[h];
            for (int k = 0; k < 256; k++)
                acc = fmaf(Xin[(size_t)gr*256+k], wval(wF1, 256, h, k), acc);
            float f = gelu_f(acc);
            hrow[h] = f;
            Hf[(size_t)gr*256+h] = f;
        }
        __syncthreads();
        for (int h = t; h < 256; h += NTH) {
            float acc = 0.0f;
            for (int k = 0; k < 256; k++)
                acc = fmaf(hrow[k], wval(wWA, 256, h, k), acc);
            grow2[h] = gelu_f(acc);
        }
        __syncthreads();
        for (int n = t; n < 64; n += NTH) {
            float acc = 0.0f;
            for (int k = 0; k < 256; k++)
                acc = fmaf(grow2[k], wval(wWB, 64, n, k), acc);
            Wt[(size_t)gr*64+n] = acc;
        }
        __syncthreads();
    }
#endif
}

// ---------------------------------------------------------------------------
// PF: P = gelu(Wt @ Sg^T) in TMEM; X = P@ff2_top + gelu(Hf)@ff2_bot + b2.
// LAST: skip X store, emit per-CTA column sums into mp instead.
// ---------------------------------------------------------------------------
template<bool LAST>
__global__ __launch_bounds__(NTH)
void gemmPF_kernel(const float* __restrict__ Wt, const char* __restrict__ sg,
                   const float* __restrict__ Hf, const char* __restrict__ wFF2,
                   const float* __restrict__ bias2, float* __restrict__ X,
                   float* __restrict__ mp, int M)
{
#if TC05_OK
    extern __shared__ __align__(1024) char sm[];
    const int t = threadIdx.x, w = t >> 5, lane = t & 31;
    const int row0 = blockIdx.x * 128;
    const uint32_t sb = smem_to_u32(sm);

    if (w == 0) TCGEN05_ALLOC(sb + 0, 512);
    if (t == 0) {
        MBARRIER_INIT(sb + 8, 1);  MBARRIER_INIT(sb + 16, 1);
        MBARRIER_INIT(sb + 24, 1); MBARRIER_INIT(sb + 32, 1);
    }
    __syncthreads();
    uint32_t tmem;
    asm volatile("ld.shared.b32 %0, [%1];" : "=r"(tmem) : "r"(sb + 0));
    const uint32_t idesc = IDESC(256);
    int fu[2] = {0, 0};

    // stage 1: D0 (cols 0..255) = Wt @ Sg^T (K=64, one chunk)
    {
        if (t < 32 && elect_one_pred()) {
            MBAR_EXPECT_TX(sb + FMB(0), 65536);
            BULK_G2S(sb + AOFF(1), sg, 65536, sb + FMB(0));   // B tile at AOFF(1)
        }
        float4 va[AITER];
        loadA4(va, Wt, row0, M, 64, 0, t);
        storeA4<false>(sm + AOFF(0), va, t);
        FENCE_ASYNC();
        __syncthreads();
        if (t < 32 && elect_one_pred()) {
            MBARRIER_WAIT_PARITY(sb + FMB(0), 0);
            mma_chunk(tmem, sb + AOFF(0), sb + AOFF(1), 16384, 32768, idesc, true);
            TCGEN05_COMMIT(sb + 8);
        }
        fu[0]++;
    }
    MBARRIER_WAIT_PARITY(sb + 8, 0);
    TCGEN05_FENCE_AFTER();
    __syncthreads();

    // stage 2: D1 (cols 256..511) = [gelu(D0) | gelu(Hf)] @ ff2  (8 chunks)
    #pragma unroll 1
    for (int c = 0; c < 8; ++c) {
        const int b = c & 1;
        uint32_t dr[8];
        float4 va[AITER];
        if (c < 4) {
            TCGEN05_LD_X8(dr, tmem + c * 64 + (w >> 2) * 8);
            TCGEN05_WAIT_LD();
        } else {
            loadA4(va, Hf, row0, M, 256, (c - 4) * 64, t);
        }
        if (c >= 2) MBARRIER_WAIT_PARITY(sb + 8 + b * 8, ((c >> 1) + (c & 1)) & 1);
        if (t < 32 && elect_one_pred()) {
            MBAR_EXPECT_TX(sb + FMB(b), 65536);
            BULK_G2S(sb + BOFF(b), wFF2 + (size_t)c * 65536, 65536, sb + FMB(b));
        }
        char* aB = sm + AOFF(b);
        if (c < 4) {
            TCGEN05_FENCE_BEFORE();
            epiA8(aB, dr, w, lane, nullptr, 0, nullptr);
        } else {
            storeA4<true>(aB, va, t);
        }
        FENCE_ASYNC();
        __syncthreads();
        if (t < 32 && elect_one_pred()) {
            MBARRIER_WAIT_PARITY(sb + FMB(b), fu[b] & 1);
            mma_chunk(tmem + 256, sb + AOFF(b), sb + BOFF(b), 16384, 32768, idesc, c == 0);
            TCGEN05_COMMIT(sb + 8 + b * 8);
        }
        fu[b]++;
    }
    MBARRIER_WAIT_PARITY(sb + 8, 0);
    MBARRIER_WAIT_PARITY(sb + 16, 1);
    TCGEN05_FENCE_AFTER();

    // epilogue: X store (or per-CTA mean partials when LAST); 32 warps, one pass
    float* mp_s = reinterpret_cast<float*>(sm + 1024);   // [4][256], pipeline done
    const int row = row0 + (w & 3) * 32 + lane;
    {
        const int j = w >> 2;            // 0..7
        uint32_t dr[32];
        TCGEN05_LD_X32(dr, tmem + 256 + j * 32);
        TCGEN05_WAIT_LD();
        #pragma unroll
        for (int c4 = 0; c4 < 8; c4++) {
            float4 v;
            v.x = __uint_as_float(dr[c4*4])   + bias2[j*32 + c4*4];
            v.y = __uint_as_float(dr[c4*4+1]) + bias2[j*32 + c4*4+1];
            v.z = __uint_as_float(dr[c4*4+2]) + bias2[j*32 + c4*4+2];
            v.w = __uint_as_float(dr[c4*4+3]) + bias2[j*32 + c4*4+3];
            if (!LAST) {
                if (row < M)
                    *reinterpret_cast<float4*>(&X[(size_t)row * 256 + j * 32 + c4 * 4]) = v;
            } else {
                if (row >= M) { v.x = v.y = v.z = v.w = 0.f; }
                v.x = wsum(v.x); v.y = wsum(v.y); v.z = wsum(v.z); v.w = wsum(v.w);
                if (lane == 0)
                    *reinterpret_cast<float4*>(&mp_s[(w & 3) * 256 + j * 32 + c4 * 4]) = v;
            }
        }
    }
    if (LAST) {
        __syncthreads();
        if (t < 256)
            mp[(size_t)blockIdx.x * 256 + t] =
                mp_s[t] + mp_s[256 + t] + mp_s[512 + t] + mp_s[768 + t];
    }
    __syncthreads();
    if (w == 0) TCGEN05_DEALLOC(tmem, 512);
#else
    __shared__ float prow[256];
    __shared__ float msum[256];
    const int row0 = blockIdx.x * 128;
    const int t = threadIdx.x;
    if (LAST) { if (t < 256) msum[t] = 0.f; __syncthreads(); }
    for (int r = 0; r < 128; r++) {
        int gr = row0 + r;
        if (gr >= M) break;
        for (int n = t; n < 256; n += NTH) {
            float acc = 0.0f;
            for (int k = 0; k < 64; k++)
                acc = fmaf(Wt[(size_t)gr*64+k], wval(sg, 256, n, k), acc);
            prow[n] = gelu_f(acc);
        }
        __syncthreads();
        for (int n = t; n < 256; n += NTH) {
            float acc = bias2[n];
            for (int k = 0; k < 256; k++)
                acc = fmaf(prow[k], wval(wFF2, 256, n, k), acc);
            for (int k = 0; k < 256; k++)
                acc = fmaf(gelu_f(Hf[(size_t)gr*256+k]), wval(wFF2, 256, n, 256 + k), acc);
            if (!LAST) X[(size_t)gr*256+n] = acc;
            else       msum[n] += acc;
        }
        __syncthreads();
    }
    if (LAST && t < 256) mp[(size_t)blockIdx.x * 256 + t] = msum[t];
#endif
}

// ---------------------------------------------------------------------------
// spartial05: S partials via tcgen05 (unchanged from R14).
// ---------------------------------------------------------------------------
__global__ __launch_bounds__(NTH)
void spartial05_kernel(const float* __restrict__ Hf, const float* __restrict__ Wt,
                       float* __restrict__ part, int N)
{
#if TC05_OK
    extern __shared__ __align__(1024) char sm[];
    const int t = threadIdx.x, w = t >> 5, lane = t & 31;
    const uint32_t sb = smem_to_u32(sm);
    const int totalChunks = (N + 63) >> 6;
    const int per = (totalChunks + SPGRID - 1) / SPGRID;
    const int cbeg = blockIdx.x * per;
    const int cend = min(totalChunks, cbeg + per);
    const int nch = cend - cbeg;
    float* myPart = part + (size_t)blockIdx.x * HDIM * MDIM;

    if (w == 0) TCGEN05_ALLOC(sb + 0, 128);
    if (t == 0) { MBARRIER_INIT(sb + 8, 1); MBARRIER_INIT(sb + 16, 1); }
    __syncthreads();
    uint32_t tmem;
    asm volatile("ld.shared.b32 %0, [%1];" : "=r"(tmem) : "r"(sb + 0));

    if (nch > 0) {
        const uint32_t idesc = IDESC(64);
        for (int ci = 0; ci < nch; ++ci) {
            const int b = ci & 1;
            if ((ci >> 1) >= 1) MBARRIER_WAIT_PARITY(sb + 8 + b * 8, ((ci >> 1) - 1) & 1);
            char* buf = sm + 1024 + b * 81920;
            const int rbeg = (cbeg + ci) * 64;

            #pragma unroll
            for (int i = 0; i < 2048 / NTH; i++) {
                int fid = t + i * NTH;
                int kp = fid & 31, hg = fid >> 5;
                int h0 = hg * 4;
                int k0 = rbeg + 2 * kp;
                float4 fa = (k0     < N) ? *reinterpret_cast<const float4*>(&Hf[(size_t)k0 * 256 + h0])
                                         : make_float4(0.f, 0.f, 0.f, 0.f);
                float4 fb = (k0 + 1 < N) ? *reinterpret_cast<const float4*>(&Hf[(size_t)(k0 + 1) * 256 + h0])
                                         : make_float4(0.f, 0.f, 0.f, 0.f);
                char* ah = buf + (h0 >> 7) * 32768;
                int r0 = h0 & 127;
                const float* pa = &fa.x;
                const float* pb = &fb.x;
                #pragma unroll
                for (int j = 0; j < 4; j++) {
                    uint32_t hp, lp;
                    split2(pa[j], pb[j], hp, lp);
                    int off = SWZ((r0 + j) * 128 + kp * 4);
                    *reinterpret_cast<uint32_t*>(ah + off)         = hp;
                    *reinterpret_cast<uint32_t*>(ah + 16384 + off) = lp;
                }
            }
            if (t < 512) {
                int kp = t & 31, mg = t >> 5;
                int m0 = mg * 4;
                int k0 = rbeg + 2 * kp;
                float4 fa = (k0     < N) ? *reinterpret_cast<const float4*>(&Wt[(size_t)k0 * 64 + m0])
                                         : make_float4(0.f, 0.f, 0.f, 0.f);
                float4 fb = (k0 + 1 < N) ? *reinterpret_cast<const float4*>(&Wt[(size_t)(k0 + 1) * 64 + m0])
                                         : make_float4(0.f, 0.f, 0.f, 0.f);
                char* bh = buf + 65536;
                const float* pa = &fa.x;
                const float* pb = &fb.x;
                #pragma unroll
                for (int j = 0; j < 4; j++) {
                    uint32_t hp, lp;
                    split2(pa[j], pb[j], hp, lp);
                    int off = SWZ((m0 + j) * 128 + kp * 4);
                    *reinterpret_cast<uint32_t*>(bh + off)        = hp;
                    *reinterpret_cast<uint32_t*>(bh + 8192 + off) = lp;
                }
            }
            FENCE_ASYNC();
            __syncthreads();
            if (t < 32 && elect_one_pred()) {
                uint32_t aBase = sb + 1024 + b * 81920;
                mma_chunk(tmem,      aBase,         aBase + 65536, 16384, 8192, idesc, ci == 0);
                mma_chunk(tmem + 64, aBase + 32768, aBase + 65536, 16384, 8192, idesc, ci == 0);
                TCGEN05_COMMIT(sb + 8 + b * 8);
            }
        }
        MBARRIER_WAIT_PARITY(sb + 8 + ((nch - 1) & 1) * 8, ((nch - 1) >> 1) & 1);
        TCGEN05_FENCE_AFTER();

        {
            int idx = w >> 2;
            if (idx < 4) {
                int mt = idx >> 1, s = idx & 1;
                uint32_t dr[32];
                TCGEN05_LD_X32(dr, tmem + mt * 64 + s * 32);
                TCGEN05_WAIT_LD();
                int h = mt * 128 + (w & 3) * 32 + lane;
                float* p = myPart + (size_t)h * 64 + s * 32;
                #pragma unroll
                for (int c4 = 0; c4 < 8; c4++)
                    *reinterpret_cast<float4*>(&p[c4 * 4]) =
                        make_float4(__uint_as_float(dr[c4*4]),   __uint_as_float(dr[c4*4+1]),
                                    __uint_as_float(dr[c4*4+2]), __uint_as_float(dr[c4*4+3]));
            }
        }
    } else {
        for (int i = t; i < HDIM * MDIM; i += NTH)
            myPart[i] = 0.0f;
    }
    __syncthreads();
    if (w == 0) TCGEN05_DEALLOC(tmem, 128);
#else
    const int t = threadIdx.x;
    const int hq = t & 127, mq = (t >> 7) & 3;
    const int totalChunks = (N + 63) >> 6;
    const int per = (totalChunks + SPGRID - 1) / SPGRID;
    const int rbeg = blockIdx.x * per * 64;
    const int rend = min(N, (blockIdx.x + 1) * per * 64);
    const int half = t >> 9;
    if (half == 0) {
        float accF[2][16];
        #pragma unroll
        for (int j = 0; j < 2; j++)
            #pragma unroll
            for (int i = 0; i < 16; i++) accF[j][i] = 0.0f;
        for (int r = rbeg; r < rend; r++) {
            float a0 = Hf[(size_t)r * HDIM + hq * 2];
            float a1 = Hf[(size_t)r * HDIM + hq * 2 + 1];
            #pragma unroll
            for (int i = 0; i < 16; i++) {
                float wv = Wt[(size_t)r * MDIM + mq * 16 + i];
                accF[0][i] = fmaf(a0, wv, accF[0][i]);
                accF[1][i] = fmaf(a1, wv, accF[1][i]);
            }
        }
        float* myPart = part + (size_t)blockIdx.x * HDIM * MDIM;
        #pragma unroll
        for (int j = 0; j < 2; j++)
            #pragma unroll
            for (int i = 0; i < 16; i++)
                myPart[(size_t)(hq * 2 + j) * MDIM + mq * 16 + i] = accF[j][i];
    }
#endif
}

// Sum SPGRID partials, gelu, emit Sg^T pre-swizzled tile.
__global__ __launch_bounds__(256)
void sfinal_kernel(const float* __restrict__ part, char* __restrict__ sg)
{
    int idx = blockIdx.x * 256 + threadIdx.x;   // h*64+m
    float s = 0.0f;
    for (int p = 0; p < SPGRID; p++)
        s += part[(size_t)p * HDIM * MDIM + idx];
    float g = gelu_f(s);
    __nv_bfloat16 h = __float2bfloat16_rn(g);
    __nv_bfloat16 l = __float2bfloat16_rn(g - __bfloat162float(h));
    int hh = idx >> 6, m = idx & 63;
    uint32_t so = SWZ(hh * 128 + m * 2);
    *reinterpret_cast<__nv_bfloat16*>(sg + so)         = h;
    *reinterpret_cast<__nv_bfloat16*>(sg + 32768 + so) = l;
}

// weight prep: single launch, chunked swizzled tile layout
__constant__ int c_wOff[9] = {0, 65536, 131072, 147456, 278528, 344064, 409600, 425984, 557056};
__constant__ int c_wK[8]   = {256, 256, 256, 512, 256, 256, 256, 512};
__constant__ int c_wNc[8]  = {256, 256, 64, 256, 256, 256, 64, 256};
__constant__ int c_wB[8]   = {0, 262144, 524288, 589824, 1114112, 1376256, 1638400, 1703936};
__global__ void transsplit_all(const float* s0, const float* s1, const float* s2, const float* s3,
                               const float* s4, const float* s5, const float* s6, const float* s7,
                               char* __restrict__ wsw)
{
    int idx = blockIdx.x * 256 + threadIdx.x;
    if (idx >= 557056) return;
    int i = 0;
    while (idx >= c_wOff[i + 1]) i++;
    const float* srcs[8] = {s0, s1, s2, s3, s4, s5, s6, s7};
    int local = idx - c_wOff[i];
    int K = c_wK[i], Nc = c_wNc[i];
    int n = local / K, k = local % K;
    float v = srcs[i][(size_t)k * Nc + n];
    __nv_bfloat16 h = __float2bfloat16_rn(v);
    __nv_bfloat16 l = __float2bfloat16_rn(v - __bfloat162float(h));
    int ch = k >> 6, kk = k & 63;
    char* base = wsw + c_wB[i] + (size_t)ch * (Nc * 256);
    uint32_t so = SWZ(n * 128 + kk * 2);
    *reinterpret_cast<__nv_bfloat16*>(base + so)            = h;
    *reinterpret_cast<__nv_bfloat16*>(base + Nc * 128 + so) = l;
}

// head: out = (sum of per-CTA partials / N) @ head_w + head_b
__global__ __launch_bounds__(256)
void head_kernel(const float* __restrict__ part, const float* __restrict__ hw,
                 const float* __restrict__ hb, float* __restrict__ out,
                 int N, int gridN)
{
    __shared__ float s[HDIM];
    int t = threadIdx.x;
    float a = 0.0f;
    for (int p = 0; p < gridN; p++) a += part[(size_t)p * HDIM + t];
    s[t] = a * (1.0f / (float)N);
    __syncthreads();
    if (t < 64) {
        float o = hb[t];
        #pragma unroll 8
        for (int h = 0; h < HDIM; h++)
            o = fmaf(s[h], hw[h * 64 + t], o);
        out[t] = o;
    }
}

// ---------------------------------------------------------------------------
// Host
// ---------------------------------------------------------------------------
extern "C" void kernel_launch(void* const* d_in, const int* in_sizes, int n_in,
                              void* d_out, int out_size)
{
    const float* x      = (const float*)d_in[0];
    const float* ff1_w0 = (const float*)d_in[2];
    const float* ff1_b0 = (const float*)d_in[3];
    const float* wA0    = (const float*)d_in[4];
    const float* wB0    = (const float*)d_in[5];
    const float* ff2_w0 = (const float*)d_in[6];
    const float* ff2_b0 = (const float*)d_in[7];
    const float* ff1_w1 = (const float*)d_in[8];
    const float* ff1_b1 = (const float*)d_in[9];
    const float* wA1    = (const float*)d_in[10];
    const float* wB1    = (const float*)d_in[11];
    const float* ff2_w1 = (const float*)d_in[12];
    const float* ff2_b1 = (const float*)d_in[13];
    const float* head_w = (const float*)d_in[14];
    const float* head_b = (const float*)d_in[15];
    float* out = (float*)d_out;

    const int N = in_sizes[0] / HDIM;
    const int grid = (N + 127) / 128;

    float *pHf, *pX, *pWt, *pPart, *pMp;
    char *pWsw, *pSg;
    cudaGetSymbolAddress((void**)&pHf,   g_Hf);
    cudaGetSymbolAddress((void**)&pX,    g_X);
    cudaGetSymbolAddress((void**)&pWt,   g_Wt);
    cudaGetSymbolAddress((void**)&pPart, g_part);
    cudaGetSymbolAddress((void**)&pMp,   g_mp);
    cudaGetSymbolAddress((void**)&pWsw,  g_wsw);
    cudaGetSymbolAddress((void**)&pSg,   g_sgsw);

    cudaFuncSetAttribute(ff1gw_kernel,         cudaFuncAttributeMaxDynamicSharedMemorySize, FSMEM);
    cudaFuncSetAttribute(gemmPF_kernel<false>, cudaFuncAttributeMaxDynamicSharedMemorySize, FSMEM);
    cudaFuncSetAttribute(gemmPF_kernel<true>,  cudaFuncAttributeMaxDynamicSharedMemorySize, FSMEM);
    cudaFuncSetAttribute(spartial05_kernel,    cudaFuncAttributeMaxDynamicSharedMemorySize, SPSMEM);

    transsplit_all<<<(557056 + 255) / 256, 256>>>(ff1_w0, wA0, wB0, ff2_w0,
                                                  ff1_w1, wA1, wB1, ff2_w1, pWsw);

    const float* Xin = x;
    const float* ff1b[2] = {ff1_b0, ff1_b1};
    const float* ff2b[2] = {ff2_b0, ff2_b1};
    for (int b = 0; b < 2; b++) {
        size_t wo = (size_t)b * WB_BLK;
        ff1gw_kernel<<<grid, NTH, FSMEM>>>(Xin,
            pWsw + wo + WB_FF1, ff1b[b],
            pWsw + wo + WB_WA, pWsw + wo + WB_WB, pHf, pWt, N);
        spartial05_kernel<<<SPGRID, NTH, SPSMEM>>>(pHf, pWt, pPart, N);
        sfinal_kernel<<<64, 256>>>(pPart, pSg);
        if (b == 0)
            gemmPF_kernel<false><<<grid, NTH, FSMEM>>>(pWt, pSg, pHf,
                pWsw + wo + WB_FF2, ff2b[b], pX, pMp, N);
        else
            gemmPF_kernel<true><<<grid, NTH, FSMEM>>>(pWt, pSg, pHf,
                pWsw + wo + WB_FF2, ff2b[b], pX, pMp, N);
        Xin = pX;
    }

    head_kernel<<<1, 256>>>(pMp, head_w, head_b, out, N, grid);
}

// round 16
// speedup vs baseline: 1.1090x; 1.0750x over previous
#include <cuda_runtime.h>
#include <cuda_bf16.h>
#include <cstdint>
#include <cstddef>

// ---------------------------------------------------------------------------
// GHM — tcgen05 pipeline v13: v12 + PF(0)+FF1GW(1) fused (X lives in TMEM,
// never hits HBM). Counter-derived mbar parities.
// ---------------------------------------------------------------------------

#if defined(__CUDA_ARCH_FEAT_SM103_ALL) || defined(__CUDA_ARCH_FEAT_SM100_ALL)
#define TC05_OK 1
#else
#define TC05_OK 0
#endif

#define NMAX 200000
#define HDIM 256
#define MDIM 64
#define NTH  1024
#define AITER (2048 / NTH)
#define SPGRID 148
#define MAXCTA 1600

__device__ float g_Hf [(size_t)NMAX * HDIM];
__device__ float g_Wt [(size_t)NMAX * MDIM];
__device__ float g_part[(size_t)SPGRID * HDIM * MDIM];
__device__ float g_mp [(size_t)MAXCTA * HDIM];
#define WB_FF1 0
#define WB_WA  262144
#define WB_WB  524288
#define WB_FF2 589824
#define WB_BLK 1114112
__device__ __align__(16) char g_wsw[2 * WB_BLK];
__device__ __align__(16) char g_sgsw[65536];     // Sg^T tile, Nc=256, K=64

__device__ __forceinline__ float gelu_f(float x) {
    return 0.5f * x * (1.0f + erff(x * 0.70710678118654752440f));
}
__device__ __forceinline__ uint32_t packbf(float lo, float hi) {
    uint32_t r;
    asm("cvt.rn.bf16x2.f32 %0, %1, %2;" : "=r"(r) : "f"(hi), "f"(lo));
    return r;
}
__device__ __forceinline__ void split2(float f0, float f1, uint32_t& h, uint32_t& l) {
    h = packbf(f0, f1);
    float fx = __uint_as_float(h << 16), fy = __uint_as_float(h & 0xffff0000u);
    l = packbf(f0 - fx, f1 - fy);
}

#define SWZ(b) ((b) ^ (((b) >> 3) & 0x70))

// fallback-only weight reconstruct
__device__ __forceinline__ float wval(const char* w, int Nc, int n, int k) {
    int ch = k >> 6, kk = k & 63;
    const char* base = w + (size_t)ch * Nc * 256;
    uint32_t so = SWZ(n * 128 + kk * 2);
    return __bfloat162float(*(const __nv_bfloat16*)(base + so)) +
           __bfloat162float(*(const __nv_bfloat16*)(base + Nc * 128 + so));
}

#if TC05_OK
__device__ __forceinline__ uint32_t elect_one_pred() {
    uint32_t pred;
    asm volatile("{\n\t.reg .pred p;\n\telect.sync _|p, 0xFFFFFFFF;\n\t"
                 "selp.b32 %0, 1, 0, p;\n\t}" : "=r"(pred));
    return pred;
}
__device__ __forceinline__ uint32_t smem_to_u32(const void* p) {
    uint32_t a;
    asm("{ .reg .u64 t; cvta.to.shared.u64 t, %1; cvt.u32.u64 %0, t; }"
        : "=r"(a) : "l"(p));
    return a;
}
#define TCGEN05_ALLOC(sa, n) \
    asm volatile("tcgen05.alloc.cta_group::1.sync.aligned.shared::cta.b32 [%0], %1;" \
                 :: "r"((uint32_t)(sa)), "r"((uint32_t)(n)) : "memory")
#define TCGEN05_DEALLOC(ta, n) \
    asm volatile("tcgen05.dealloc.cta_group::1.sync.aligned.b32 %0, %1;" \
                 :: "r"(ta), "r"((uint32_t)(n)))
#define TCGEN05_COMMIT(mb) \
    asm volatile("tcgen05.commit.cta_group::1.mbarrier::arrive::one.shared::cluster.b64 [%0];" \
                 :: "r"((uint32_t)(mb)) : "memory")
#define TCGEN05_WAIT_LD()  asm volatile("tcgen05.wait::ld.sync.aligned;" ::: "memory")
#define TCGEN05_FENCE_AFTER()  asm volatile("tcgen05.fence::after_thread_sync;" ::: "memory")
#define TCGEN05_FENCE_BEFORE() asm volatile("tcgen05.fence::before_thread_sync;" ::: "memory")
#define FENCE_ASYNC() asm volatile("fence.proxy.async.shared::cta;" ::: "memory")
#define MBARRIER_INIT(mb, c) \
    asm volatile("mbarrier.init.shared.b64 [%0], %1;" :: "r"((uint32_t)(mb)), "r"((uint32_t)(c)) : "memory")
#define MBAR_EXPECT_TX(mb, bytes) \
    asm volatile("mbarrier.arrive.expect_tx.shared.b64 _, [%0], %1;" \
                 :: "r"((uint32_t)(mb)), "r"((uint32_t)(bytes)) : "memory")
#define BULK_G2S(dst, src, bytes, mb) \
    asm volatile("cp.async.bulk.shared::cta.global.mbarrier::complete_tx::bytes [%0], [%1], %2, [%3];" \
                 :: "r"((uint32_t)(dst)), "l"(src), "r"((uint32_t)(bytes)), "r"((uint32_t)(mb)) : "memory")
#define MBARRIER_WAIT_PARITY(mb, ph) do { \
    uint32_t _m = (uint32_t)(mb), _p = (uint32_t)(ph), _d; \
    asm volatile("{\n\t.reg .pred p;\n\t" \
        "mbarrier.try_wait.parity.acquire.cta.shared::cta.b64 p, [%1], %2;\n\t" \
        "selp.b32 %0, 1, 0, p;\n\t}" : "=r"(_d) : "r"(_m), "r"(_p) : "memory"); \
    if (!_d) { \
        asm volatile("{\n\t.reg .pred P1;\n\tWL_%=: \n\t" \
            "mbarrier.try_wait.parity.acquire.cta.shared::cta.b64 P1, [%0], %1, 0x989680;\n\t" \
            "@P1 bra.uni WD_%=;\n\tbra.uni WL_%=;\n\tWD_%=: \n\t}" \
            :: "r"(_m), "r"(_p) : "memory"); \
    } } while (0)
#define TCGEN05_LD_X32(r, ta) \
    asm volatile("tcgen05.ld.sync.aligned.32x32b.x32.b32 " \
        "{%0,%1,%2,%3,%4,%5,%6,%7,%8,%9,%10,%11,%12,%13,%14,%15," \
        "%16,%17,%18,%19,%20,%21,%22,%23,%24,%25,%26,%27,%28,%29,%30,%31}, [%32];" \
        : "=r"((r)[0]),"=r"((r)[1]),"=r"((r)[2]),"=r"((r)[3]),"=r"((r)[4]),"=r"((r)[5]), \
          "=r"((r)[6]),"=r"((r)[7]),"=r"((r)[8]),"=r"((r)[9]),"=r"((r)[10]),"=r"((r)[11]), \
          "=r"((r)[12]),"=r"((r)[13]),"=r"((r)[14]),"=r"((r)[15]),"=r"((r)[16]),"=r"((r)[17]), \
          "=r"((r)[18]),"=r"((r)[19]),"=r"((r)[20]),"=r"((r)[21]),"=r"((r)[22]),"=r"((r)[23]), \
          "=r"((r)[24]),"=r"((r)[25]),"=r"((r)[26]),"=r"((r)[27]),"=r"((r)[28]),"=r"((r)[29]), \
          "=r"((r)[30]),"=r"((r)[31]) : "r"(ta))
#define TCGEN05_LD_X8(r, ta) \
    asm volatile("tcgen05.ld.sync.aligned.32x32b.x8.b32 " \
        "{%0,%1,%2,%3,%4,%5,%6,%7}, [%8];" \
        : "=r"((r)[0]),"=r"((r)[1]),"=r"((r)[2]),"=r"((r)[3]), \
          "=r"((r)[4]),"=r"((r)[5]),"=r"((r)[6]),"=r"((r)[7]) : "r"(ta))

static constexpr uint64_t SMEM_DESC_BASE_SW128 =
    (uint64_t(2) << 61) | (uint64_t(1) << 46) | (uint64_t(64) << 32) | (uint64_t(1) << 16);
#define MAKE_SMEM_DESC(a) (SMEM_DESC_BASE_SW128 | ((uint64_t)((a) >> 4) & 0x3FFF))

__device__ __forceinline__ void mma_f16_ss(uint32_t d, uint64_t ad, uint64_t bd,
                                           uint32_t idesc, uint32_t en) {
    asm volatile("{\n\t.reg .pred p;\n\tsetp.ne.u32 p, %5, 0;\n\t"
        "tcgen05.mma.cta_group::1.kind::f16 [%0], %1, %2, %3, {%4,%4,%4,%4}, p;\n\t}"
        :: "r"(d), "l"(ad), "l"(bd), "r"(idesc), "r"(0u), "r"(en) : "memory");
}

__device__ __forceinline__ void mma_chunk(uint32_t d, uint32_t sb_ah, uint32_t sb_bh,
                                          int aL, int bL, uint32_t idesc, bool first) {
    const uint64_t adh = MAKE_SMEM_DESC(sb_ah), adl = MAKE_SMEM_DESC(sb_ah + aL);
    const uint64_t bdh = MAKE_SMEM_DESC(sb_bh), bdl = MAKE_SMEM_DESC(sb_bh + bL);
    #pragma unroll
    for (int ks = 0; ks < 4; ks++) {
        uint64_t off = (uint64_t)(ks * 2);
        mma_f16_ss(d, adh + off, bdh + off, idesc, (first && ks == 0) ? 0u : 1u);
        mma_f16_ss(d, adh + off, bdl + off, idesc, 1u);
        mma_f16_ss(d, adl + off, bdh + off, idesc, 1u);
    }
}
#endif // TC05_OK

#define IDESC(Nc) ((1u << 4) | (1u << 7) | (1u << 10) | ((uint32_t)((Nc) / 8) << 17) | (8u << 24))
#define AOFF(b)  (1024 + (b) * 32768)
#define BOFF(b)  (66560 + (b) * 65536)
#define FSMEM    197632
#define SPSMEM   (1024 + 2 * 81920)
#define FMB(b)   (24 + (b) * 8)

#if TC05_OK
__device__ __forceinline__ void loadA4(float4* va, const float* A, int row0, int M,
                                       int strideK, int kc0, int t) {
    #pragma unroll
    for (int i = 0; i < AITER; i++) {
        int fid = t + i * NTH;
        int r = fid >> 4, c16 = fid & 15;
        int gr = row0 + r;
        va[i] = make_float4(0.f, 0.f, 0.f, 0.f);
        if (gr < M)
            va[i] = *reinterpret_cast<const float4*>(&A[(size_t)gr * strideK + kc0 + c16 * 4]);
    }
}
template<bool GELU_A>
__device__ __forceinline__ void storeA4(char* aB, const float4* va, int t) {
    #pragma unroll
    for (int i = 0; i < AITER; i++) {
        int fid = t + i * NTH;
        int r = fid >> 4, c16 = fid & 15;
        float4 v = va[i];
        if (GELU_A) { v.x = gelu_f(v.x); v.y = gelu_f(v.y); v.z = gelu_f(v.z); v.w = gelu_f(v.w); }
        uint32_t h0, l0, h1, l1;
        split2(v.x, v.y, h0, l0);
        split2(v.z, v.w, h1, l1);
        int swo = SWZ(r * 128 + c16 * 8);
        *reinterpret_cast<uint2*>(aB + swo)         = make_uint2(h0, h1);
        *reinterpret_cast<uint2*>(aB + 16384 + swo) = make_uint2(l0, l1);
    }
}
// 32-warp TMEM-sourced A-tile producer (LDTM.x8): seg = w>>2, sub = w&3.
template<bool GELU>
__device__ __forceinline__ void epiA8(char* aB, const uint32_t* dr, int w, int lane,
                                      const float* bias, int colBase,
                                      float* HfRow /*or null*/) {
    const int seg = w >> 2;
    const int r = (w & 3) * 32 + lane;
    #pragma unroll
    for (int q = 0; q < 2; q++) {
        float f0 = __uint_as_float(dr[4*q]);
        float f1 = __uint_as_float(dr[4*q+1]);
        float f2 = __uint_as_float(dr[4*q+2]);
        float f3 = __uint_as_float(dr[4*q+3]);
        if (bias) {
            int col = colBase + seg * 8 + 4 * q;
            f0 += bias[col]; f1 += bias[col+1]; f2 += bias[col+2]; f3 += bias[col+3];
        }
        if (GELU) { f0 = gelu_f(f0); f1 = gelu_f(f1); f2 = gelu_f(f2); f3 = gelu_f(f3); }
        if (HfRow)
            *reinterpret_cast<float4*>(&HfRow[colBase + seg * 8 + 4 * q]) =
                make_float4(f0, f1, f2, f3);
        uint32_t h0, l0, h1, l1;
        split2(f0, f1, h0, l0);
        split2(f2, f3, h1, l1);
        int off = SWZ(r * 128 + seg * 16 + q * 8);
        *reinterpret_cast<uint2*>(aB + off)         = make_uint2(h0, h1);
        *reinterpret_cast<uint2*>(aB + 16384 + off) = make_uint2(l0, l1);
    }
}
__device__ __forceinline__ float wsum(float v) {
    #pragma unroll
    for (int o = 16; o > 0; o >>= 1)
        v += __shfl_xor_sync(0xffffffffu, v, o);
    return v;
}
#endif

// ---------------------------------------------------------------------------
// ff1gw (block 0 only): Hf = gelu(Xin@ff1+b1); Wt = gelu(Hf@wA)@wB.
// ---------------------------------------------------------------------------
__global__ __launch_bounds__(NTH)
void ff1gw_kernel(const float* __restrict__ Xin,
                  const char* __restrict__ wF1, const float* __restrict__ bias1,
                  const char* __restrict__ wWA, const char* __restrict__ wWB,
                  float* __restrict__ Hf, float* __restrict__ Wt, int M)
{
#if TC05_OK
    extern __shared__ __align__(1024) char sm[];
    const int t = threadIdx.x, w = t >> 5, lane = t & 31;
    const int row0 = blockIdx.x * 128;
    const uint32_t sb = smem_to_u32(sm);

    if (w == 0) TCGEN05_ALLOC(sb + 0, 512);
    if (t == 0) {
        MBARRIER_INIT(sb + 8, 1);  MBARRIER_INIT(sb + 16, 1);
        MBARRIER_INIT(sb + 24, 1); MBARRIER_INIT(sb + 32, 1);
    }
    __syncthreads();
    uint32_t tmem;
    asm volatile("ld.shared.b32 %0, [%1];" : "=r"(tmem) : "r"(sb + 0));
    int fu[2] = {0, 0}, mu[2] = {0, 0};

    // stage 0: D0 = Xin @ ff1
    {
        float4 va[AITER];
        loadA4(va, Xin, row0, M, 256, 0, t);
        for (int c = 0; c < 4; ++c) {
            const int b = c & 1;
            if (mu[b] > 0) MBARRIER_WAIT_PARITY(sb + 8 + b * 8, (mu[b] - 1) & 1);
            if (t < 32 && elect_one_pred()) {
                MBAR_EXPECT_TX(sb + FMB(b), 65536);
                BULK_G2S(sb + BOFF(b), wF1 + (size_t)c * 65536, 65536, sb + FMB(b));
            }
            storeA4<false>(sm + AOFF(b), va, t);
            if (c < 3) loadA4(va, Xin, row0, M, 256, (c + 1) * 64, t);
            FENCE_ASYNC();
            __syncthreads();
            if (t < 32 && elect_one_pred()) {
                MBARRIER_WAIT_PARITY(sb + FMB(b), fu[b] & 1);
                mma_chunk(tmem, sb + AOFF(b), sb + BOFF(b), 16384, 32768, IDESC(256), c == 0);
                TCGEN05_COMMIT(sb + 8 + b * 8);
            }
            fu[b]++; mu[b]++;
        }
    }
    MBARRIER_WAIT_PARITY(sb + 8,  (mu[0] - 1) & 1);
    MBARRIER_WAIT_PARITY(sb + 16, (mu[1] - 1) & 1);
    TCGEN05_FENCE_AFTER();

    // stage 1: D1 = gelu(D0+b1)@wA ; write Hf
    {
        const int grow = row0 + (w & 3) * 32 + lane;
        float* HfRow = (grow < M) ? &Hf[(size_t)grow * 256] : nullptr;
        for (int c = 0; c < 4; ++c) {
            const int b = c & 1;
            uint32_t dr[8];
            TCGEN05_LD_X8(dr, tmem + c * 64 + (w >> 2) * 8);
            TCGEN05_WAIT_LD();
            if (mu[b] > 0) MBARRIER_WAIT_PARITY(sb + 8 + b * 8, (mu[b] - 1) & 1);
            if (t < 32 && elect_one_pred()) {
                MBAR_EXPECT_TX(sb + FMB(b), 65536);
                BULK_G2S(sb + BOFF(b), wWA + (size_t)c * 65536, 65536, sb + FMB(b));
            }
            TCGEN05_FENCE_BEFORE();
            epiA8<true>(sm + AOFF(b), dr, w, lane, bias1, c * 64, HfRow);
            FENCE_ASYNC();
            __syncthreads();
            if (t < 32 && elect_one_pred()) {
                MBARRIER_WAIT_PARITY(sb + FMB(b), fu[b] & 1);
                mma_chunk(tmem + 256, sb + AOFF(b), sb + BOFF(b), 16384, 32768, IDESC(256), c == 0);
                TCGEN05_COMMIT(sb + 8 + b * 8);
            }
            fu[b]++; mu[b]++;
        }
    }
    MBARRIER_WAIT_PARITY(sb + 8,  (mu[0] - 1) & 1);
    MBARRIER_WAIT_PARITY(sb + 16, (mu[1] - 1) & 1);
    TCGEN05_FENCE_AFTER();

    // stage 2: D0(0..63) = gelu(D1)@wB
    for (int c = 0; c < 4; ++c) {
        const int b = c & 1;
        uint32_t dr[8];
        TCGEN05_LD_X8(dr, tmem + 256 + c * 64 + (w >> 2) * 8);
        TCGEN05_WAIT_LD();
        if (mu[b] > 0) MBARRIER_WAIT_PARITY(sb + 8 + b * 8, (mu[b] - 1) & 1);
        if (t < 32 && elect_one_pred()) {
            MBAR_EXPECT_TX(sb + FMB(b), 16384);
            BULK_G2S(sb + BOFF(b), wWB + (size_t)c * 16384, 16384, sb + FMB(b));
        }
        TCGEN05_FENCE_BEFORE();
        epiA8<true>(sm + AOFF(b), dr, w, lane, nullptr, 0, nullptr);
        FENCE_ASYNC();
        __syncthreads();
        if (t < 32 && elect_one_pred()) {
            MBARRIER_WAIT_PARITY(sb + FMB(b), fu[b] & 1);
            mma_chunk(tmem, sb + AOFF(b), sb + BOFF(b), 16384, 8192, IDESC(64), c == 0);
            TCGEN05_COMMIT(sb + 8 + b * 8);
        }
        fu[b]++; mu[b]++;
    }
    MBARRIER_WAIT_PARITY(sb + 8,  (mu[0] - 1) & 1);
    MBARRIER_WAIT_PARITY(sb + 16, (mu[1] - 1) & 1);
    TCGEN05_FENCE_AFTER();

    // epilogue: Wt fp32 from D0 cols 0..63
    {
        int j = w >> 2;
        if (j < 2) {
            uint32_t dr[32];
            TCGEN05_LD_X32(dr, tmem + j * 32);
            TCGEN05_WAIT_LD();
            const int row = row0 + (w & 3) * 32 + lane;
            if (row < M) {
                #pragma unroll
                for (int c4 = 0; c4 < 8; c4++)
                    *reinterpret_cast<float4*>(&Wt[(size_t)row * 64 + j * 32 + c4 * 4]) =
                        make_float4(__uint_as_float(dr[c4*4]),   __uint_as_float(dr[c4*4+1]),
                                    __uint_as_float(dr[c4*4+2]), __uint_as_float(dr[c4*4+3]));
            }
        }
    }
    __syncthreads();
    if (w == 0) TCGEN05_DEALLOC(tmem, 512);
#else
    __shared__ float hrow[256], grow2[256];
    const int row0 = blockIdx.x * 128;
    const int t = threadIdx.x;
    for (int r = 0; r < 128; r++) {
        int gr = row0 + r;
        if (gr >= M) break;
        for (int h = t; h < 256; h += NTH) {
            float acc = bias1[h];
            for (int k = 0; k < 256; k++)
                acc = fmaf(Xin[(size_t)gr*256+k], wval(wF1, 256, h, k), acc);
            float f = gelu_f(acc);
            hrow[h] = f;
            Hf[(size_t)gr*256+h] = f;
        }
        __syncthreads();
        for (int h = t; h < 256; h += NTH) {
            float acc = 0.0f;
            for (int k = 0; k < 256; k++)
                acc = fmaf(hrow[k], wval(wWA, 256, h, k), acc);
            grow2[h] = gelu_f(acc);
        }
        __syncthreads();
        for (int n = t; n < 64; n += NTH) {
            float acc = 0.0f;
            for (int k = 0; k < 256; k++)
                acc = fmaf(grow2[k], wval(wWB, 64, n, k), acc);
            Wt[(size_t)gr*64+n] = acc;
        }
        __syncthreads();
    }
#endif
}

// ---------------------------------------------------------------------------
// pfff1: PF(block0) + FF1GW(block1) fused. X stays in TMEM.
//   D0 = Wt@Sg^T (P raw); D1 = [gelu(D0)|gelu(Hf)]@ff2 (X-b2 raw);
//   D0' = (D1+b2)@ff1n; D1' = gelu(D0'+b1n)@wAn (writes HfOut);
//   D0(0..63) = gelu(D1')@wBn -> WtOut.
// ---------------------------------------------------------------------------
__global__ __launch_bounds__(NTH)
void pfff1_kernel(const float* __restrict__ Wt, const char* __restrict__ sg,
                  const float* __restrict__ Hf, const char* __restrict__ wFF2,
                  const float* __restrict__ bias2,
                  const char* __restrict__ wF1n, const float* __restrict__ bias1n,
                  const char* __restrict__ wWAn, const char* __restrict__ wWBn,
                  float* __restrict__ HfOut, float* __restrict__ WtOut, int M)
{
#if TC05_OK
    extern __shared__ __align__(1024) char sm[];
    const int t = threadIdx.x, w = t >> 5, lane = t & 31;
    const int row0 = blockIdx.x * 128;
    const uint32_t sb = smem_to_u32(sm);

    if (w == 0) TCGEN05_ALLOC(sb + 0, 512);
    if (t == 0) {
        MBARRIER_INIT(sb + 8, 1);  MBARRIER_INIT(sb + 16, 1);
        MBARRIER_INIT(sb + 24, 1); MBARRIER_INIT(sb + 32, 1);
    }
    __syncthreads();
    uint32_t tmem;
    asm volatile("ld.shared.b32 %0, [%1];" : "=r"(tmem) : "r"(sb + 0));
    const uint32_t idesc = IDESC(256);
    int fu[2] = {0, 0}, mu[2] = {0, 0};

    // PF stage 1: D0 = Wt @ Sg^T (single chunk)
    {
        if (t < 32 && elect_one_pred()) {
            MBAR_EXPECT_TX(sb + FMB(0), 65536);
            BULK_G2S(sb + AOFF(1), sg, 65536, sb + FMB(0));
        }
        float4 va[AITER];
        loadA4(va, Wt, row0, M, 64, 0, t);
        storeA4<false>(sm + AOFF(0), va, t);
        FENCE_ASYNC();
        __syncthreads();
        if (t < 32 && elect_one_pred()) {
            MBARRIER_WAIT_PARITY(sb + FMB(0), fu[0] & 1);
            mma_chunk(tmem, sb + AOFF(0), sb + AOFF(1), 16384, 32768, idesc, true);
            TCGEN05_COMMIT(sb + 8);
        }
        fu[0]++; mu[0]++;
    }
    MBARRIER_WAIT_PARITY(sb + 8, (mu[0] - 1) & 1);
    TCGEN05_FENCE_AFTER();
    __syncthreads();

    // PF stage 2: D1 = [gelu(D0) | gelu(Hf)] @ ff2 (8 chunks)
    #pragma unroll 1
    for (int c = 0; c < 8; ++c) {
        const int b = c & 1;
        uint32_t dr[8];
        float4 va[AITER];
        if (c < 4) {
            TCGEN05_LD_X8(dr, tmem + c * 64 + (w >> 2) * 8);
            TCGEN05_WAIT_LD();
        } else {
            loadA4(va, Hf, row0, M, 256, (c - 4) * 64, t);
        }
        if (mu[b] > 0) MBARRIER_WAIT_PARITY(sb + 8 + b * 8, (mu[b] - 1) & 1);
        if (t < 32 && elect_one_pred()) {
            MBAR_EXPECT_TX(sb + FMB(b), 65536);
            BULK_G2S(sb + BOFF(b), wFF2 + (size_t)c * 65536, 65536, sb + FMB(b));
        }
        char* aB = sm + AOFF(b);
        if (c < 4) {
            TCGEN05_FENCE_BEFORE();
            epiA8<true>(aB, dr, w, lane, nullptr, 0, nullptr);
        } else {
            storeA4<true>(aB, va, t);
        }
        FENCE_ASYNC();
        __syncthreads();
        if (t < 32 && elect_one_pred()) {
            MBARRIER_WAIT_PARITY(sb + FMB(b), fu[b] & 1);
            mma_chunk(tmem + 256, sb + AOFF(b), sb + BOFF(b), 16384, 32768, idesc, c == 0);
            TCGEN05_COMMIT(sb + 8 + b * 8);
        }
        fu[b]++; mu[b]++;
    }
    MBARRIER_WAIT_PARITY(sb + 8,  (mu[0] - 1) & 1);
    MBARRIER_WAIT_PARITY(sb + 16, (mu[1] - 1) & 1);
    TCGEN05_FENCE_AFTER();

    // FF1 stage 0': D0 = (D1 + b2) @ ff1n   (A = X from TMEM, no gelu)
    for (int c = 0; c < 4; ++c) {
        const int b = c & 1;
        uint32_t dr[8];
        TCGEN05_LD_X8(dr, tmem + 256 + c * 64 + (w >> 2) * 8);
        TCGEN05_WAIT_LD();
        if (mu[b] > 0) MBARRIER_WAIT_PARITY(sb + 8 + b * 8, (mu[b] - 1) & 1);
        if (t < 32 && elect_one_pred()) {
            MBAR_EXPECT_TX(sb + FMB(b), 65536);
            BULK_G2S(sb + BOFF(b), wF1n + (size_t)c * 65536, 65536, sb + FMB(b));
        }
        TCGEN05_FENCE_BEFORE();
        epiA8<false>(sm + AOFF(b), dr, w, lane, bias2, c * 64, nullptr);
        FENCE_ASYNC();
        __syncthreads();
        if (t < 32 && elect_one_pred()) {
            MBARRIER_WAIT_PARITY(sb + FMB(b), fu[b] & 1);
            mma_chunk(tmem, sb + AOFF(b), sb + BOFF(b), 16384, 32768, idesc, c == 0);
            TCGEN05_COMMIT(sb + 8 + b * 8);
        }
        fu[b]++; mu[b]++;
    }
    MBARRIER_WAIT_PARITY(sb + 8,  (mu[0] - 1) & 1);
    MBARRIER_WAIT_PARITY(sb + 16, (mu[1] - 1) & 1);
    TCGEN05_FENCE_AFTER();

    // FF1 stage 1': D1 = gelu(D0 + b1n) @ wAn ; write HfOut
    {
        const int grow = row0 + (w & 3) * 32 + lane;
        float* HfRow = (grow < M) ? &HfOut[(size_t)grow * 256] : nullptr;
        for (int c = 0; c < 4; ++c) {
            const int b = c & 1;
            uint32_t dr[8];
            TCGEN05_LD_X8(dr, tmem + c * 64 + (w >> 2) * 8);
            TCGEN05_WAIT_LD();
            if (mu[b] > 0) MBARRIER_WAIT_PARITY(sb + 8 + b * 8, (mu[b] - 1) & 1);
            if (t < 32 && elect_one_pred()) {
                MBAR_EXPECT_TX(sb + FMB(b), 65536);
                BULK_G2S(sb + BOFF(b), wWAn + (size_t)c * 65536, 65536, sb + FMB(b));
            }
            TCGEN05_FENCE_BEFORE();
            epiA8<true>(sm + AOFF(b), dr, w, lane, bias1n, c * 64, HfRow);
            FENCE_ASYNC();
            __syncthreads();
            if (t < 32 && elect_one_pred()) {
                MBARRIER_WAIT_PARITY(sb + FMB(b), fu[b] & 1);
                mma_chunk(tmem + 256, sb + AOFF(b), sb + BOFF(b), 16384, 32768, idesc, c == 0);
                TCGEN05_COMMIT(sb + 8 + b * 8);
            }
            fu[b]++; mu[b]++;
        }
    }
    MBARRIER_WAIT_PARITY(sb + 8,  (mu[0] - 1) & 1);
    MBARRIER_WAIT_PARITY(sb + 16, (mu[1] - 1) & 1);
    TCGEN05_FENCE_AFTER();

    // FF1 stage 2': D0(0..63) = gelu(D1) @ wBn
    for (int c = 0; c < 4; ++c) {
        const int b = c & 1;
        uint32_t dr[8];
        TCGEN05_LD_X8(dr, tmem + 256 + c * 64 + (w >> 2) * 8);
        TCGEN05_WAIT_LD();
        if (mu[b] > 0) MBARRIER_WAIT_PARITY(sb + 8 + b * 8, (mu[b] - 1) & 1);
        if (t < 32 && elect_one_pred()) {
            MBAR_EXPECT_TX(sb + FMB(b), 16384);
            BULK_G2S(sb + BOFF(b), wWBn + (size_t)c * 16384, 16384, sb + FMB(b));
        }
        TCGEN05_FENCE_BEFORE();
        epiA8<true>(sm + AOFF(b), dr, w, lane, nullptr, 0, nullptr);
        FENCE_ASYNC();
        __syncthreads();
        if (t < 32 && elect_one_pred()) {
            MBARRIER_WAIT_PARITY(sb + FMB(b), fu[b] & 1);
            mma_chunk(tmem, sb + AOFF(b), sb + BOFF(b), 16384, 8192, IDESC(64), c == 0);
            TCGEN05_COMMIT(sb + 8 + b * 8);
        }
        fu[b]++; mu[b]++;
    }
    MBARRIER_WAIT_PARITY(sb + 8,  (mu[0] - 1) & 1);
    MBARRIER_WAIT_PARITY(sb + 16, (mu[1] - 1) & 1);
    TCGEN05_FENCE_AFTER();

    // epilogue: WtOut from D0 cols 0..63
    {
        int j = w >> 2;
        if (j < 2) {
            uint32_t dr[32];
            TCGEN05_LD_X32(dr, tmem + j * 32);
            TCGEN05_WAIT_LD();
            const int row = row0 + (w & 3) * 32 + lane;
            if (row < M) {
                #pragma unroll
                for (int c4 = 0; c4 < 8; c4++)
                    *reinterpret_cast<float4*>(&WtOut[(size_t)row * 64 + j * 32 + c4 * 4]) =
                        make_float4(__uint_as_float(dr[c4*4]),   __uint_as_float(dr[c4*4+1]),
                                    __uint_as_float(dr[c4*4+2]), __uint_as_float(dr[c4*4+3]));
            }
        }
    }
    __syncthreads();
    if (w == 0) TCGEN05_DEALLOC(tmem, 512);
#else
    __shared__ float prow[256], xrow[256], hrow[256], grow2[256];
    const int row0 = blockIdx.x * 128;
    const int t = threadIdx.x;
    for (int r = 0; r < 128; r++) {
        int gr = row0 + r;
        if (gr >= M) break;
        for (int n = t; n < 256; n += NTH) {
            float acc = 0.0f;
            for (int k = 0; k < 64; k++)
                acc = fmaf(Wt[(size_t)gr*64+k], wval(sg, 256, n, k), acc);
            prow[n] = gelu_f(acc);
        }
        __syncthreads();
        for (int n = t; n < 256; n += NTH) {
            float acc = bias2[n];
            for (int k = 0; k < 256; k++)
                acc = fmaf(prow[k], wval(wFF2, 256, n, k), acc);
            for (int k = 0; k < 256; k++)
                acc = fmaf(gelu_f(Hf[(size_t)gr*256+k]), wval(wFF2, 256, n, 256 + k), acc);
            xrow[n] = acc;
        }
        __syncthreads();
        for (int h = t; h < 256; h += NTH) {
            float acc = bias1n[h];
            for (int k = 0; k < 256; k++)
                acc = fmaf(xrow[k], wval(wF1n, 256, h, k), acc);
            float f = gelu_f(acc);
            hrow[h] = f;
            HfOut[(size_t)gr*256+h] = f;
        }
        __syncthreads();
        for (int h = t; h < 256; h += NTH) {
            float acc = 0.0f;
            for (int k = 0; k < 256; k++)
                acc = fmaf(hrow[k], wval(wWAn, 256, h, k), acc);
            grow2[h] = gelu_f(acc);
        }
        __syncthreads();
        for (int n = t; n < 64; n += NTH) {
            float acc = 0.0f;
            for (int k = 0; k < 256; k++)
                acc = fmaf(grow2[k], wval(wWBn, 64, n, k), acc);
            WtOut[(size_t)gr*64+n] = acc;
        }
        __syncthreads();
    }
#endif
}

// ---------------------------------------------------------------------------
// PF (block 1, LAST): P = gelu(Wt@Sg^T); mean-partials of X into mp.
// ---------------------------------------------------------------------------
__global__ __launch_bounds__(NTH)
void gemmPF_last_kernel(const float* __restrict__ Wt, const char* __restrict__ sg,
                        const float* __restrict__ Hf, const char* __restrict__ wFF2,
                        const float* __restrict__ bias2, float* __restrict__ mp, int M)
{
#if TC05_OK
    extern __shared__ __align__(1024) char sm[];
    const int t = threadIdx.x, w = t >> 5, lane = t & 31;
    const int row0 = blockIdx.x * 128;
    const uint32_t sb = smem_to_u32(sm);

    if (w == 0) TCGEN05_ALLOC(sb + 0, 512);
    if (t == 0) {
        MBARRIER_INIT(sb + 8, 1);  MBARRIER_INIT(sb + 16, 1);
        MBARRIER_INIT(sb + 24, 1); MBARRIER_INIT(sb + 32, 1);
    }
    __syncthreads();
    uint32_t tmem;
    asm volatile("ld.shared.b32 %0, [%1];" : "=r"(tmem) : "r"(sb + 0));
    const uint32_t idesc = IDESC(256);
    int fu[2] = {0, 0}, mu[2] = {0, 0};

    {
        if (t < 32 && elect_one_pred()) {
            MBAR_EXPECT_TX(sb + FMB(0), 65536);
            BULK_G2S(sb + AOFF(1), sg, 65536, sb + FMB(0));
        }
        float4 va[AITER];
        loadA4(va, Wt, row0, M, 64, 0, t);
        storeA4<false>(sm + AOFF(0), va, t);
        FENCE_ASYNC();
        __syncthreads();
        if (t < 32 && elect_one_pred()) {
            MBARRIER_WAIT_PARITY(sb + FMB(0), fu[0] & 1);
            mma_chunk(tmem, sb + AOFF(0), sb + AOFF(1), 16384, 32768, idesc, true);
            TCGEN05_COMMIT(sb + 8);
        }
        fu[0]++; mu[0]++;
    }
    MBARRIER_WAIT_PARITY(sb + 8, (mu[0] - 1) & 1);
    TCGEN05_FENCE_AFTER();
    __syncthreads();

    #pragma unroll 1
    for (int c = 0; c < 8; ++c) {
        const int b = c & 1;
        uint32_t dr[8];
        float4 va[AITER];
        if (c < 4) {
            TCGEN05_LD_X8(dr, tmem + c * 64 + (w >> 2) * 8);
            TCGEN05_WAIT_LD();
        } else {
            loadA4(va, Hf, row0, M, 256, (c - 4) * 64, t);
        }
        if (mu[b] > 0) MBARRIER_WAIT_PARITY(sb + 8 + b * 8, (mu[b] - 1) & 1);
        if (t < 32 && elect_one_pred()) {
            MBAR_EXPECT_TX(sb + FMB(b), 65536);
            BULK_G2S(sb + BOFF(b), wFF2 + (size_t)c * 65536, 65536, sb + FMB(b));
        }
        char* aB = sm + AOFF(b);
        if (c < 4) {
            TCGEN05_FENCE_BEFORE();
            epiA8<true>(aB, dr, w, lane, nullptr, 0, nullptr);
        } else {
            storeA4<true>(aB, va, t);
        }
        FENCE_ASYNC();
        __syncthreads();
        if (t < 32 && elect_one_pred()) {
            MBARRIER_WAIT_PARITY(sb + FMB(b), fu[b] & 1);
            mma_chunk(tmem + 256, sb + AOFF(b), sb + BOFF(b), 16384, 32768, idesc, c == 0);
            TCGEN05_COMMIT(sb + 8 + b * 8);
        }
        fu[b]++; mu[b]++;
    }
    MBARRIER_WAIT_PARITY(sb + 8,  (mu[0] - 1) & 1);
    MBARRIER_WAIT_PARITY(sb + 16, (mu[1] - 1) & 1);
    TCGEN05_FENCE_AFTER();

    float* mp_s = reinterpret_cast<float*>(sm + 1024);
    const int row = row0 + (w & 3) * 32 + lane;
    {
        const int j = w >> 2;
        uint32_t dr[32];
        TCGEN05_LD_X32(dr, tmem + 256 + j * 32);
        TCGEN05_WAIT_LD();
        #pragma unroll
        for (int c4 = 0; c4 < 8; c4++) {
            float4 v;
            v.x = __uint_as_float(dr[c4*4])   + bias2[j*32 + c4*4];
            v.y = __uint_as_float(dr[c4*4+1]) + bias2[j*32 + c4*4+1];
            v.z = __uint_as_float(dr[c4*4+2]) + bias2[j*32 + c4*4+2];
            v.w = __uint_as_float(dr[c4*4+3]) + bias2[j*32 + c4*4+3];
            if (row >= M) { v.x = v.y = v.z = v.w = 0.f; }
            v.x = wsum(v.x); v.y = wsum(v.y); v.z = wsum(v.z); v.w = wsum(v.w);
            if (lane == 0)
                *reinterpret_cast<float4*>(&mp_s[(w & 3) * 256 + j * 32 + c4 * 4]) = v;
        }
    }
    __syncthreads();
    if (t < 256)
        mp[(size_t)blockIdx.x * 256 + t] =
            mp_s[t] + mp_s[256 + t] + mp_s[512 + t] + mp_s[768 + t];
    __syncthreads();
    if (w == 0) TCGEN05_DEALLOC(tmem, 512);
#else
    __shared__ float prow[256];
    __shared__ float msum[256];
    const int row0 = blockIdx.x * 128;
    const int t = threadIdx.x;
    if (t < 256) msum[t] = 0.f;
    __syncthreads();
    for (int r = 0; r < 128; r++) {
        int gr = row0 + r;
        if (gr >= M) break;
        for (int n = t; n < 256; n += NTH) {
            float acc = 0.0f;
            for (int k = 0; k < 64; k++)
                acc = fmaf(Wt[(size_t)gr*64+k], wval(sg, 256, n, k), acc);
            prow[n] = gelu_f(acc);
        }
        __syncthreads();
        for (int n = t; n < 256; n += NTH) {
            float acc = bias2[n];
            for (int k = 0; k < 256; k++)
                acc = fmaf(prow[k], wval(wFF2, 256, n, k), acc);
            for (int k = 0; k < 256; k++)
                acc = fmaf(gelu_f(Hf[(size_t)gr*256+k]), wval(wFF2, 256, n, 256 + k), acc);
            msum[n] += acc;
        }
        __syncthreads();
    }
    if (t < 256) mp[(size_t)blockIdx.x * 256 + t] = msum[t];
#endif
}

// ---------------------------------------------------------------------------
// spartial05: S partials via tcgen05 (unchanged from R15).
// ---------------------------------------------------------------------------
__global__ __launch_bounds__(NTH)
void spartial05_kernel(const float* __restrict__ Hf, const float* __restrict__ Wt,
                       float* __restrict__ part, int N)
{
#if TC05_OK
    extern __shared__ __align__(1024) char sm[];
    const int t = threadIdx.x, w = t >> 5, lane = t & 31;
    const uint32_t sb = smem_to_u32(sm);
    const int totalChunks = (N + 63) >> 6;
    const int per = (totalChunks + SPGRID - 1) / SPGRID;
    const int cbeg = blockIdx.x * per;
    const int cend = min(totalChunks, cbeg + per);
    const int nch = cend - cbeg;
    float* myPart = part + (size_t)blockIdx.x * HDIM * MDIM;

    if (w == 0) TCGEN05_ALLOC(sb + 0, 128);
    if (t == 0) { MBARRIER_INIT(sb + 8, 1); MBARRIER_INIT(sb + 16, 1); }
    __syncthreads();
    uint32_t tmem;
    asm volatile("ld.shared.b32 %0, [%1];" : "=r"(tmem) : "r"(sb + 0));

    if (nch > 0) {
        const uint32_t idesc = IDESC(64);
        for (int ci = 0; ci < nch; ++ci) {
            const int b = ci & 1;
            if ((ci >> 1) >= 1) MBARRIER_WAIT_PARITY(sb + 8 + b * 8, ((ci >> 1) - 1) & 1);
            char* buf = sm + 1024 + b * 81920;
            const int rbeg = (cbeg + ci) * 64;

            #pragma unroll
            for (int i = 0; i < 2048 / NTH; i++) {
                int fid = t + i * NTH;
                int kp = fid & 31, hg = fid >> 5;
                int h0 = hg * 4;
                int k0 = rbeg + 2 * kp;
                float4 fa = (k0     < N) ? *reinterpret_cast<const float4*>(&Hf[(size_t)k0 * 256 + h0])
                                         : make_float4(0.f, 0.f, 0.f, 0.f);
                float4 fb = (k0 + 1 < N) ? *reinterpret_cast<const float4*>(&Hf[(size_t)(k0 + 1) * 256 + h0])
                                         : make_float4(0.f, 0.f, 0.f, 0.f);
                char* ah = buf + (h0 >> 7) * 32768;
                int r0 = h0 & 127;
                const float* pa = &fa.x;
                const float* pb = &fb.x;
                #pragma unroll
                for (int j = 0; j < 4; j++) {
                    uint32_t hp, lp;
                    split2(pa[j], pb[j], hp, lp);
                    int off = SWZ((r0 + j) * 128 + kp * 4);
                    *reinterpret_cast<uint32_t*>(ah + off)         = hp;
                    *reinterpret_cast<uint32_t*>(ah + 16384 + off) = lp;
                }
            }
            if (t < 512) {
                int kp = t & 31, mg = t >> 5;
                int m0 = mg * 4;
                int k0 = rbeg + 2 * kp;
                float4 fa = (k0     < N) ? *reinterpret_cast<const float4*>(&Wt[(size_t)k0 * 64 + m0])
                                         : make_float4(0.f, 0.f, 0.f, 0.f);
                float4 fb = (k0 + 1 < N) ? *reinterpret_cast<const float4*>(&Wt[(size_t)(k0 + 1) * 64 + m0])
                                         : make_float4(0.f, 0.f, 0.f, 0.f);
                char* bh = buf + 65536;
                const float* pa = &fa.x;
                const float* pb = &fb.x;
                #pragma unroll
                for (int j = 0; j < 4; j++) {
                    uint32_t hp, lp;
                    split2(pa[j], pb[j], hp, lp);
                    int off = SWZ((m0 + j) * 128 + kp * 4);
                    *reinterpret_cast<uint32_t*>(bh + off)        = hp;
                    *reinterpret_cast<uint32_t*>(bh + 8192 + off) = lp;
                }
            }
            FENCE_ASYNC();
            __syncthreads();
            if (t < 32 && elect_one_pred()) {
                uint32_t aBase = sb + 1024 + b * 81920;
                mma_chunk(tmem,      aBase,         aBase + 65536, 16384, 8192, idesc, ci == 0);
                mma_chunk(tmem + 64, aBase + 32768, aBase + 65536, 16384, 8192, idesc, ci == 0);
                TCGEN05_COMMIT(sb + 8 + b * 8);
            }
        }
        MBARRIER_WAIT_PARITY(sb + 8 + ((nch - 1) & 1) * 8, ((nch - 1) >> 1) & 1);
        TCGEN05_FENCE_AFTER();

        {
            int idx = w >> 2;
            if (idx < 4) {
                int mt = idx >> 1, s = idx & 1;
                uint32_t dr[32];
                TCGEN05_LD_X32(dr, tmem + mt * 64 + s * 32);
                TCGEN05_WAIT_LD();
                int h = mt * 128 + (w & 3) * 32 + lane;
                float* p = myPart + (size_t)h * 64 + s * 32;
                #pragma unroll
                for (int c4 = 0; c4 < 8; c4++)
                    *reinterpret_cast<float4*>(&p[c4 * 4]) =
                        make_float4(__uint_as_float(dr[c4*4]),   __uint_as_float(dr[c4*4+1]),
                                    __uint_as_float(dr[c4*4+2]), __uint_as_float(dr[c4*4+3]));
            }
        }
    } else {
        for (int i = t; i < HDIM * MDIM; i += NTH)
            myPart[i] = 0.0f;
    }
    __syncthreads();
    if (w == 0) TCGEN05_DEALLOC(tmem, 128);
#else
    const int t = threadIdx.x;
    const int hq = t & 127, mq = (t >> 7) & 3;
    const int totalChunks = (N + 63) >> 6;
    const int per = (totalChunks + SPGRID - 1) / SPGRID;
    const int rbeg = blockIdx.x * per * 64;
    const int rend = min(N, (blockIdx.x + 1) * per * 64);
    const int half = t >> 9;
    if (half == 0) {
        float accF[2][16];
        #pragma unroll
        for (int j = 0; j < 2; j++)
            #pragma unroll
            for (int i = 0; i < 16; i++) accF[j][i] = 0.0f;
        for (int r = rbeg; r < rend; r++) {
            float a0 = Hf[(size_t)r * HDIM + hq * 2];
            float a1 = Hf[(size_t)r * HDIM + hq * 2 + 1];
            #pragma unroll
            for (int i = 0; i < 16; i++) {
                float wv = Wt[(size_t)r * MDIM + mq * 16 + i];
                accF[0][i] = fmaf(a0, wv, accF[0][i]);
                accF[1][i] = fmaf(a1, wv, accF[1][i]);
            }
        }
        float* myPart = part + (size_t)blockIdx.x * HDIM * MDIM;
        #pragma unroll
        for (int j = 0; j < 2; j++)
            #pragma unroll
            for (int i = 0; i < 16; i++)
                myPart[(size_t)(hq * 2 + j) * MDIM + mq * 16 + i] = accF[j][i];
    }
#endif
}

// Sum SPGRID partials, gelu, emit Sg^T pre-swizzled tile.
__global__ __launch_bounds__(256)
void sfinal_kernel(const float* __restrict__ part, char* __restrict__ sg)
{
    int idx = blockIdx.x * 256 + threadIdx.x;   // h*64+m
    float s = 0.0f;
    for (int p = 0; p < SPGRID; p++)
        s += part[(size_t)p * HDIM * MDIM + idx];
    float g = gelu_f(s);
    __nv_bfloat16 h = __float2bfloat16_rn(g);
    __nv_bfloat16 l = __float2bfloat16_rn(g - __bfloat162float(h));
    int hh = idx >> 6, m = idx & 63;
    uint32_t so = SWZ(hh * 128 + m * 2);
    *reinterpret_cast<__nv_bfloat16*>(sg + so)         = h;
    *reinterpret_cast<__nv_bfloat16*>(sg + 32768 + so) = l;
}

// weight prep: single launch, chunked swizzled tile layout
__constant__ int c_wOff[9] = {0, 65536, 131072, 147456, 278528, 344064, 409600, 425984, 557056};
__constant__ int c_wK[8]   = {256, 256, 256, 512, 256, 256, 256, 512};
__constant__ int c_wNc[8]  = {256, 256, 64, 256, 256, 256, 64, 256};
__constant__ int c_wB[8]   = {0, 262144, 524288, 589824, 1114112, 1376256, 1638400, 1703936};
__global__ void transsplit_all(const float* s0, const float* s1, const float* s2, const float* s3,
                               const float* s4, const float* s5, const float* s6, const float* s7,
                               char* __restrict__ wsw)
{
    int idx = blockIdx.x * 256 + threadIdx.x;
    if (idx >= 557056) return;
    int i = 0;
    while (idx >= c_wOff[i + 1]) i++;
    const float* srcs[8] = {s0, s1, s2, s3, s4, s5, s6, s7};
    int local = idx - c_wOff[i];
    int K = c_wK[i], Nc = c_wNc[i];
    int n = local / K, k = local % K;
    float v = srcs[i][(size_t)k * Nc + n];
    __nv_bfloat16 h = __float2bfloat16_rn(v);
    __nv_bfloat16 l = __float2bfloat16_rn(v - __bfloat162float(h));
    int ch = k >> 6, kk = k & 63;
    char* base = wsw + c_wB[i] + (size_t)ch * (Nc * 256);
    uint32_t so = SWZ(n * 128 + kk * 2);
    *reinterpret_cast<__nv_bfloat16*>(base + so)            = h;
    *reinterpret_cast<__nv_bfloat16*>(base + Nc * 128 + so) = l;
}

// head: out = (sum of per-CTA partials / N) @ head_w + head_b
__global__ __launch_bounds__(256)
void head_kernel(const float* __restrict__ part, const float* __restrict__ hw,
                 const float* __restrict__ hb, float* __restrict__ out,
                 int N, int gridN)
{
    __shared__ float s[HDIM];
    int t = threadIdx.x;
    float a = 0.0f;
    for (int p = 0; p < gridN; p++) a += part[(size_t)p * HDIM + t];
    s[t] = a * (1.0f / (float)N);
    __syncthreads();
    if (t < 64) {
        float o = hb[t];
        #pragma unroll 8
        for (int h = 0; h < HDIM; h++)
            o = fmaf(s[h], hw[h * 64 + t], o);
        out[t] = o;
    }
}

// ---------------------------------------------------------------------------
// Host
// ---------------------------------------------------------------------------
extern "C" void kernel_launch(void* const* d_in, const int* in_sizes, int n_in,
                              void* d_out, int out_size)
{
    const float* x      = (const float*)d_in[0];
    const float* ff1_w0 = (const float*)d_in[2];
    const float* ff1_b0 = (const float*)d_in[3];
    const float* wA0    = (const float*)d_in[4];
    const float* wB0    = (const float*)d_in[5];
    const float* ff2_w0 = (const float*)d_in[6];
    const float* ff2_b0 = (const float*)d_in[7];
    const float* ff1_w1 = (const float*)d_in[8];
    const float* ff1_b1 = (const float*)d_in[9];
    const float* wA1    = (const float*)d_in[10];
    const float* wB1    = (const float*)d_in[11];
    const float* ff2_w1 = (const float*)d_in[12];
    const float* ff2_b1 = (const float*)d_in[13];
    const float* head_w = (const float*)d_in[14];
    const float* head_b = (const float*)d_in[15];
    float* out = (float*)d_out;

    const int N = in_sizes[0] / HDIM;
    const int grid = (N + 127) / 128;

    float *pHf, *pWt, *pPart, *pMp;
    char *pWsw, *pSg;
    cudaGetSymbolAddress((void**)&pHf,   g_Hf);
    cudaGetSymbolAddress((void**)&pWt,   g_Wt);
    cudaGetSymbolAddress((void**)&pPart, g_part);
    cudaGetSymbolAddress((void**)&pMp,   g_mp);
    cudaGetSymbolAddress((void**)&pWsw,  g_wsw);
    cudaGetSymbolAddress((void**)&pSg,   g_sgsw);

    cudaFuncSetAttribute(ff1gw_kernel,      cudaFuncAttributeMaxDynamicSharedMemorySize, FSMEM);
    cudaFuncSetAttribute(pfff1_kernel,      cudaFuncAttributeMaxDynamicSharedMemorySize, FSMEM);
    cudaFuncSetAttribute(gemmPF_last_kernel,cudaFuncAttributeMaxDynamicSharedMemorySize, FSMEM);
    cudaFuncSetAttribute(spartial05_kernel, cudaFuncAttributeMaxDynamicSharedMemorySize, SPSMEM);

    transsplit_all<<<(557056 + 255) / 256, 256>>>(ff1_w0, wA0, wB0, ff2_w0,
                                                  ff1_w1, wA1, wB1, ff2_w1, pWsw);

    // block 0 front half
    ff1gw_kernel<<<grid, NTH, FSMEM>>>(x,
        pWsw + WB_FF1, ff1_b0, pWsw + WB_WA, pWsw + WB_WB, pHf, pWt, N);
    spartial05_kernel<<<SPGRID, NTH, SPSMEM>>>(pHf, pWt, pPart, N);
    sfinal_kernel<<<64, 256>>>(pPart, pSg);

    // fused: PF(block0) + FF1GW(block1); X never hits HBM
    pfff1_kernel<<<grid, NTH, FSMEM>>>(pWt, pSg, pHf,
        pWsw + WB_FF2, ff2_b0,
        pWsw + WB_BLK + WB_FF1, ff1_b1,
        pWsw + WB_BLK + WB_WA, pWsw + WB_BLK + WB_WB,
        pHf, pWt, N);
    spartial05_kernel<<<SPGRID, NTH, SPSMEM>>>(pHf, pWt, pPart, N);
    sfinal_kernel<<<64, 256>>>(pPart, pSg);

    // block 1 back half with fused mean partials
    gemmPF_last_kernel<<<grid, NTH, FSMEM>>>(pWt, pSg, pHf,
        pWsw + WB_BLK + WB_FF2, ff2_b1, pMp, N);

    head_kernel<<<1, 256>>>(pMp, head_w, head_b, out, N, grid);
}

// round 17
// speedup vs baseline: 1.1168x; 1.0070x over previous
#include <cuda_runtime.h>
#include <cuda_bf16.h>
#include <cstdint>
#include <cstddef>

// ---------------------------------------------------------------------------
// GHM — tcgen05 pipeline v14: v13 + fast branch-free erf-GELU (A&S 7.1.26).
// Rationale: with bulk fills + x8 epilogues, the gelu ALU hump (~1900 cyc/chunk
// with erff) is now co-critical with the 1800-cyc MMA floor.
// ---------------------------------------------------------------------------

#if defined(__CUDA_ARCH_FEAT_SM103_ALL) || defined(__CUDA_ARCH_FEAT_SM100_ALL)
#define TC05_OK 1
#else
#define TC05_OK 0
#endif

#define NMAX 200000
#define HDIM 256
#define MDIM 64
#define NTH  1024
#define AITER (2048 / NTH)
#define SPGRID 148
#define MAXCTA 1600

__device__ float g_Hf [(size_t)NMAX * HDIM];
__device__ float g_Wt [(size_t)NMAX * MDIM];
__device__ float g_part[(size_t)SPGRID * HDIM * MDIM];
__device__ float g_mp [(size_t)MAXCTA * HDIM];
#define WB_FF1 0
#define WB_WA  262144
#define WB_WB  524288
#define WB_FF2 589824
#define WB_BLK 1114112
__device__ __align__(16) char g_wsw[2 * WB_BLK];
__device__ __align__(16) char g_sgsw[65536];     // Sg^T tile, Nc=256, K=64

// ---- fast exact-erf gelu: A&S 7.1.26, |abs err| < 1.5e-7, branch-free ----
__device__ __forceinline__ float fast_rcp(float x) {
    float r; asm("rcp.approx.f32 %0, %1;" : "=f"(r) : "f"(x)); return r;
}
__device__ __forceinline__ float fast_ex2(float x) {
    float r; asm("ex2.approx.f32 %0, %1;" : "=f"(r) : "f"(x)); return r;
}
__device__ __forceinline__ float gelu_f(float x) {
    float u = 0.70710678118654752440f * x;
    float a = fabsf(u);
    float t = fast_rcp(fmaf(0.3275911f, a, 1.0f));
    float poly = t * fmaf(t, fmaf(t, fmaf(t, fmaf(t, 1.061405429f, -1.453152027f),
                                          1.421413741f), -0.284496736f), 0.254829592f);
    float e = fast_ex2(-a * a * 1.4426950408889634f);
    float erf_abs = fmaf(-poly, e, 1.0f);
    float erf = copysignf(erf_abs, u);
    return 0.5f * x * (1.0f + erf);
}

__device__ __forceinline__ uint32_t packbf(float lo, float hi) {
    uint32_t r;
    asm("cvt.rn.bf16x2.f32 %0, %1, %2;" : "=r"(r) : "f"(hi), "f"(lo));
    return r;
}
__device__ __forceinline__ void split2(float f0, float f1, uint32_t& h, uint32_t& l) {
    h = packbf(f0, f1);
    float fx = __uint_as_float(h << 16), fy = __uint_as_float(h & 0xffff0000u);
    l = packbf(f0 - fx, f1 - fy);
}

#define SWZ(b) ((b) ^ (((b) >> 3) & 0x70))

// fallback-only weight reconstruct
__device__ __forceinline__ float wval(const char* w, int Nc, int n, int k) {
    int ch = k >> 6, kk = k & 63;
    const char* base = w + (size_t)ch * Nc * 256;
    uint32_t so = SWZ(n * 128 + kk * 2);
    return __bfloat162float(*(const __nv_bfloat16*)(base + so)) +
           __bfloat162float(*(const __nv_bfloat16*)(base + Nc * 128 + so));
}

#if TC05_OK
__device__ __forceinline__ uint32_t elect_one_pred() {
    uint32_t pred;
    asm volatile("{\n\t.reg .pred p;\n\telect.sync _|p, 0xFFFFFFFF;\n\t"
                 "selp.b32 %0, 1, 0, p;\n\t}" : "=r"(pred));
    return pred;
}
__device__ __forceinline__ uint32_t smem_to_u32(const void* p) {
    uint32_t a;
    asm("{ .reg .u64 t; cvta.to.shared.u64 t, %1; cvt.u32.u64 %0, t; }"
        : "=r"(a) : "l"(p));
    return a;
}
#define TCGEN05_ALLOC(sa, n) \
    asm volatile("tcgen05.alloc.cta_group::1.sync.aligned.shared::cta.b32 [%0], %1;" \
                 :: "r"((uint32_t)(sa)), "r"((uint32_t)(n)) : "memory")
#define TCGEN05_DEALLOC(ta, n) \
    asm volatile("tcgen05.dealloc.cta_group::1.sync.aligned.b32 %0, %1;" \
                 :: "r"(ta), "r"((uint32_t)(n)))
#define TCGEN05_COMMIT(mb) \
    asm volatile("tcgen05.commit.cta_group::1.mbarrier::arrive::one.shared::cluster.b64 [%0];" \
                 :: "r"((uint32_t)(mb)) : "memory")
#define TCGEN05_WAIT_LD()  asm volatile("tcgen05.wait::ld.sync.aligned;" ::: "memory")
#define TCGEN05_FENCE_AFTER()  asm volatile("tcgen05.fence::after_thread_sync;" ::: "memory")
#define TCGEN05_FENCE_BEFORE() asm volatile("tcgen05.fence::before_thread_sync;" ::: "memory")
#define FENCE_ASYNC() asm volatile("fence.proxy.async.shared::cta;" ::: "memory")
#define MBARRIER_INIT(mb, c) \
    asm volatile("mbarrier.init.shared.b64 [%0], %1;" :: "r"((uint32_t)(mb)), "r"((uint32_t)(c)) : "memory")
#define MBAR_EXPECT_TX(mb, bytes) \
    asm volatile("mbarrier.arrive.expect_tx.shared.b64 _, [%0], %1;" \
                 :: "r"((uint32_t)(mb)), "r"((uint32_t)(bytes)) : "memory")
#define BULK_G2S(dst, src, bytes, mb) \
    asm volatile("cp.async.bulk.shared::cta.global.mbarrier::complete_tx::bytes [%0], [%1], %2, [%3];" \
                 :: "r"((uint32_t)(dst)), "l"(src), "r"((uint32_t)(bytes)), "r"((uint32_t)(mb)) : "memory")
#define MBARRIER_WAIT_PARITY(mb, ph) do { \
    uint32_t _m = (uint32_t)(mb), _p = (uint32_t)(ph), _d; \
    asm volatile("{\n\t.reg .pred p;\n\t" \
        "mbarrier.try_wait.parity.acquire.cta.shared::cta.b64 p, [%1], %2;\n\t" \
        "selp.b32 %0, 1, 0, p;\n\t}" : "=r"(_d) : "r"(_m), "r"(_p) : "memory"); \
    if (!_d) { \
        asm volatile("{\n\t.reg .pred P1;\n\tWL_%=: \n\t" \
            "mbarrier.try_wait.parity.acquire.cta.shared::cta.b64 P1, [%0], %1, 0x989680;\n\t" \
            "@P1 bra.uni WD_%=;\n\tbra.uni WL_%=;\n\tWD_%=: \n\t}" \
            :: "r"(_m), "r"(_p) : "memory"); \
    } } while (0)
#define TCGEN05_LD_X32(r, ta) \
    asm volatile("tcgen05.ld.sync.aligned.32x32b.x32.b32 " \
        "{%0,%1,%2,%3,%4,%5,%6,%7,%8,%9,%10,%11,%12,%13,%14,%15," \
        "%16,%17,%18,%19,%20,%21,%22,%23,%24,%25,%26,%27,%28,%29,%30,%31}, [%32];" \
        : "=r"((r)[0]),"=r"((r)[1]),"=r"((r)[2]),"=r"((r)[3]),"=r"((r)[4]),"=r"((r)[5]), \
          "=r"((r)[6]),"=r"((r)[7]),"=r"((r)[8]),"=r"((r)[9]),"=r"((r)[10]),"=r"((r)[11]), \
          "=r"((r)[12]),"=r"((r)[13]),"=r"((r)[14]),"=r"((r)[15]),"=r"((r)[16]),"=r"((r)[17]), \
          "=r"((r)[18]),"=r"((r)[19]),"=r"((r)[20]),"=r"((r)[21]),"=r"((r)[22]),"=r"((r)[23]), \
          "=r"((r)[24]),"=r"((r)[25]),"=r"((r)[26]),"=r"((r)[27]),"=r"((r)[28]),"=r"((r)[29]), \
          "=r"((r)[30]),"=r"((r)[31]) : "r"(ta))
#define TCGEN05_LD_X8(r, ta) \
    asm volatile("tcgen05.ld.sync.aligned.32x32b.x8.b32 " \
        "{%0,%1,%2,%3,%4,%5,%6,%7}, [%8];" \
        : "=r"((r)[0]),"=r"((r)[1]),"=r"((r)[2]),"=r"((r)[3]), \
          "=r"((r)[4]),"=r"((r)[5]),"=r"((r)[6]),"=r"((r)[7]) : "r"(ta))

static constexpr uint64_t SMEM_DESC_BASE_SW128 =
    (uint64_t(2) << 61) | (uint64_t(1) << 46) | (uint64_t(64) << 32) | (uint64_t(1) << 16);
#define MAKE_SMEM_DESC(a) (SMEM_DESC_BASE_SW128 | ((uint64_t)((a) >> 4) & 0x3FFF))

__device__ __forceinline__ void mma_f16_ss(uint32_t d, uint64_t ad, uint64_t bd,
                                           uint32_t idesc, uint32_t en) {
    asm volatile("{\n\t.reg .pred p;\n\tsetp.ne.u32 p, %5, 0;\n\t"
        "tcgen05.mma.cta_group::1.kind::f16 [%0], %1, %2, %3, {%4,%4,%4,%4}, p;\n\t}"
        :: "r"(d), "l"(ad), "l"(bd), "r"(idesc), "r"(0u), "r"(en) : "memory");
}

__device__ __forceinline__ void mma_chunk(uint32_t d, uint32_t sb_ah, uint32_t sb_bh,
                                          int aL, int bL, uint32_t idesc, bool first) {
    const uint64_t adh = MAKE_SMEM_DESC(sb_ah), adl = MAKE_SMEM_DESC(sb_ah + aL);
    const uint64_t bdh = MAKE_SMEM_DESC(sb_bh), bdl = MAKE_SMEM_DESC(sb_bh + bL);
    #pragma unroll
    for (int ks = 0; ks < 4; ks++) {
        uint64_t off = (uint64_t)(ks * 2);
        mma_f16_ss(d, adh + off, bdh + off, idesc, (first && ks == 0) ? 0u : 1u);
        mma_f16_ss(d, adh + off, bdl + off, idesc, 1u);
        mma_f16_ss(d, adl + off, bdh + off, idesc, 1u);
    }
}
#endif // TC05_OK

#define IDESC(Nc) ((1u << 4) | (1u << 7) | (1u << 10) | ((uint32_t)((Nc) / 8) << 17) | (8u << 24))
#define AOFF(b)  (1024 + (b) * 32768)
#define BOFF(b)  (66560 + (b) * 65536)
#define FSMEM    197632
#define SPSMEM   (1024 + 2 * 81920)
#define FMB(b)   (24 + (b) * 8)

#if TC05_OK
__device__ __forceinline__ void loadA4(float4* va, const float* A, int row0, int M,
                                       int strideK, int kc0, int t) {
    #pragma unroll
    for (int i = 0; i < AITER; i++) {
        int fid = t + i * NTH;
        int r = fid >> 4, c16 = fid & 15;
        int gr = row0 + r;
        va[i] = make_float4(0.f, 0.f, 0.f, 0.f);
        if (gr < M)
            va[i] = *reinterpret_cast<const float4*>(&A[(size_t)gr * strideK + kc0 + c16 * 4]);
    }
}
template<bool GELU_A>
__device__ __forceinline__ void storeA4(char* aB, const float4* va, int t) {
    #pragma unroll
    for (int i = 0; i < AITER; i++) {
        int fid = t + i * NTH;
        int r = fid >> 4, c16 = fid & 15;
        float4 v = va[i];
        if (GELU_A) { v.x = gelu_f(v.x); v.y = gelu_f(v.y); v.z = gelu_f(v.z); v.w = gelu_f(v.w); }
        uint32_t h0, l0, h1, l1;
        split2(v.x, v.y, h0, l0);
        split2(v.z, v.w, h1, l1);
        int swo = SWZ(r * 128 + c16 * 8);
        *reinterpret_cast<uint2*>(aB + swo)         = make_uint2(h0, h1);
        *reinterpret_cast<uint2*>(aB + 16384 + swo) = make_uint2(l0, l1);
    }
}
// 32-warp TMEM-sourced A-tile producer (LDTM.x8): seg = w>>2, sub = w&3.
template<bool GELU>
__device__ __forceinline__ void epiA8(char* aB, const uint32_t* dr, int w, int lane,
                                      const float* bias, int colBase,
                                      float* HfRow /*or null*/) {
    const int seg = w >> 2;
    const int r = (w & 3) * 32 + lane;
    #pragma unroll
    for (int q = 0; q < 2; q++) {
        float f0 = __uint_as_float(dr[4*q]);
        float f1 = __uint_as_float(dr[4*q+1]);
        float f2 = __uint_as_float(dr[4*q+2]);
        float f3 = __uint_as_float(dr[4*q+3]);
        if (bias) {
            int col = colBase + seg * 8 + 4 * q;
            f0 += bias[col]; f1 += bias[col+1]; f2 += bias[col+2]; f3 += bias[col+3];
        }
        if (GELU) { f0 = gelu_f(f0); f1 = gelu_f(f1); f2 = gelu_f(f2); f3 = gelu_f(f3); }
        if (HfRow)
            *reinterpret_cast<float4*>(&HfRow[colBase + seg * 8 + 4 * q]) =
                make_float4(f0, f1, f2, f3);
        uint32_t h0, l0, h1, l1;
        split2(f0, f1, h0, l0);
        split2(f2, f3, h1, l1);
        int off = SWZ(r * 128 + seg * 16 + q * 8);
        *reinterpret_cast<uint2*>(aB + off)         = make_uint2(h0, h1);
        *reinterpret_cast<uint2*>(aB + 16384 + off) = make_uint2(l0, l1);
    }
}
__device__ __forceinline__ float wsum(float v) {
    #pragma unroll
    for (int o = 16; o > 0; o >>= 1)
        v += __shfl_xor_sync(0xffffffffu, v, o);
    return v;
}
#endif

// ---------------------------------------------------------------------------
// ff1gw (block 0 only): Hf = gelu(Xin@ff1+b1); Wt = gelu(Hf@wA)@wB.
// ---------------------------------------------------------------------------
__global__ __launch_bounds__(NTH)
void ff1gw_kernel(const float* __restrict__ Xin,
                  const char* __restrict__ wF1, const float* __restrict__ bias1,
                  const char* __restrict__ wWA, const char* __restrict__ wWB,
                  float* __restrict__ Hf, float* __restrict__ Wt, int M)
{
#if TC05_OK
    extern __shared__ __align__(1024) char sm[];
    const int t = threadIdx.x, w = t >> 5, lane = t & 31;
    const int row0 = blockIdx.x * 128;
    const uint32_t sb = smem_to_u32(sm);

    if (w == 0) TCGEN05_ALLOC(sb + 0, 512);
    if (t == 0) {
        MBARRIER_INIT(sb + 8, 1);  MBARRIER_INIT(sb + 16, 1);
        MBARRIER_INIT(sb + 24, 1); MBARRIER_INIT(sb + 32, 1);
    }
    __syncthreads();
    uint32_t tmem;
    asm volatile("ld.shared.b32 %0, [%1];" : "=r"(tmem) : "r"(sb + 0));
    int fu[2] = {0, 0}, mu[2] = {0, 0};

    // stage 0: D0 = Xin @ ff1
    {
        float4 va[AITER];
        loadA4(va, Xin, row0, M, 256, 0, t);
        for (int c = 0; c < 4; ++c) {
            const int b = c & 1;
            if (mu[b] > 0) MBARRIER_WAIT_PARITY(sb + 8 + b * 8, (mu[b] - 1) & 1);
            if (t < 32 && elect_one_pred()) {
                MBAR_EXPECT_TX(sb + FMB(b), 65536);
                BULK_G2S(sb + BOFF(b), wF1 + (size_t)c * 65536, 65536, sb + FMB(b));
            }
            storeA4<false>(sm + AOFF(b), va, t);
            if (c < 3) loadA4(va, Xin, row0, M, 256, (c + 1) * 64, t);
            FENCE_ASYNC();
            __syncthreads();
            if (t < 32 && elect_one_pred()) {
                MBARRIER_WAIT_PARITY(sb + FMB(b), fu[b] & 1);
                mma_chunk(tmem, sb + AOFF(b), sb + BOFF(b), 16384, 32768, IDESC(256), c == 0);
                TCGEN05_COMMIT(sb + 8 + b * 8);
            }
            fu[b]++; mu[b]++;
        }
    }
    MBARRIER_WAIT_PARITY(sb + 8,  (mu[0] - 1) & 1);
    MBARRIER_WAIT_PARITY(sb + 16, (mu[1] - 1) & 1);
    TCGEN05_FENCE_AFTER();

    // stage 1: D1 = gelu(D0+b1)@wA ; write Hf
    {
        const int grow = row0 + (w & 3) * 32 + lane;
        float* HfRow = (grow < M) ? &Hf[(size_t)grow * 256] : nullptr;
        for (int c = 0; c < 4; ++c) {
            const int b = c & 1;
            uint32_t dr[8];
            TCGEN05_LD_X8(dr, tmem + c * 64 + (w >> 2) * 8);
            TCGEN05_WAIT_LD();
            if (mu[b] > 0) MBARRIER_WAIT_PARITY(sb + 8 + b * 8, (mu[b] - 1) & 1);
            if (t < 32 && elect_one_pred()) {
                MBAR_EXPECT_TX(sb + FMB(b), 65536);
                BULK_G2S(sb + BOFF(b), wWA + (size_t)c * 65536, 65536, sb + FMB(b));
            }
            TCGEN05_FENCE_BEFORE();
            epiA8<true>(sm + AOFF(b), dr, w, lane, bias1, c * 64, HfRow);
            FENCE_ASYNC();
            __syncthreads();
            if (t < 32 && elect_one_pred()) {
                MBARRIER_WAIT_PARITY(sb + FMB(b), fu[b] & 1);
                mma_chunk(tmem + 256, sb + AOFF(b), sb + BOFF(b), 16384, 32768, IDESC(256), c == 0);
                TCGEN05_COMMIT(sb + 8 + b * 8);
            }
            fu[b]++; mu[b]++;
        }
    }
    MBARRIER_WAIT_PARITY(sb + 8,  (mu[0] - 1) & 1);
    MBARRIER_WAIT_PARITY(sb + 16, (mu[1] - 1) & 1);
    TCGEN05_FENCE_AFTER();

    // stage 2: D0(0..63) = gelu(D1)@wB
    for (int c = 0; c < 4; ++c) {
        const int b = c & 1;
        uint32_t dr[8];
        TCGEN05_LD_X8(dr, tmem + 256 + c * 64 + (w >> 2) * 8);
        TCGEN05_WAIT_LD();
        if (mu[b] > 0) MBARRIER_WAIT_PARITY(sb + 8 + b * 8, (mu[b] - 1) & 1);
        if (t < 32 && elect_one_pred()) {
            MBAR_EXPECT_TX(sb + FMB(b), 16384);
            BULK_G2S(sb + BOFF(b), wWB + (size_t)c * 16384, 16384, sb + FMB(b));
        }
        TCGEN05_FENCE_BEFORE();
        epiA8<true>(sm + AOFF(b), dr, w, lane, nullptr, 0, nullptr);
        FENCE_ASYNC();
        __syncthreads();
        if (t < 32 && elect_one_pred()) {
            MBARRIER_WAIT_PARITY(sb + FMB(b), fu[b] & 1);
            mma_chunk(tmem, sb + AOFF(b), sb + BOFF(b), 16384, 8192, IDESC(64), c == 0);
            TCGEN05_COMMIT(sb + 8 + b * 8);
        }
        fu[b]++; mu[b]++;
    }
    MBARRIER_WAIT_PARITY(sb + 8,  (mu[0] - 1) & 1);
    MBARRIER_WAIT_PARITY(sb + 16, (mu[1] - 1) & 1);
    TCGEN05_FENCE_AFTER();

    // epilogue: Wt fp32 from D0 cols 0..63
    {
        int j = w >> 2;
        if (j < 2) {
            uint32_t dr[32];
            TCGEN05_LD_X32(dr, tmem + j * 32);
            TCGEN05_WAIT_LD();
            const int row = row0 + (w & 3) * 32 + lane;
            if (row < M) {
                #pragma unroll
                for (int c4 = 0; c4 < 8; c4++)
                    *reinterpret_cast<float4*>(&Wt[(size_t)row * 64 + j * 32 + c4 * 4]) =
                        make_float4(__uint_as_float(dr[c4*4]),   __uint_as_float(dr[c4*4+1]),
                                    __uint_as_float(dr[c4*4+2]), __uint_as_float(dr[c4*4+3]));
            }
        }
    }
    __syncthreads();
    if (w == 0) TCGEN05_DEALLOC(tmem, 512);
#else
    __shared__ float hrow[256], grow2[256];
    const int row0 = blockIdx.x * 128;
    const int t = threadIdx.x;
    for (int r = 0; r < 128; r++) {
        int gr = row0 + r;
        if (gr >= M) break;
        for (int h = t; h < 256; h += NTH) {
            float acc = bias1[h];
            for (int k = 0; k < 256; k++)
                acc = fmaf(Xin[(size_t)gr*256+k], wval(wF1, 256, h, k), acc);
            float f = gelu_f(acc);
            hrow[h] = f;
            Hf[(size_t)gr*256+h] = f;
        }
        __syncthreads();
        for (int h = t; h < 256; h += NTH) {
            float acc = 0.0f;
            for (int k = 0; k < 256; k++)
                acc = fmaf(hrow[k], wval(wWA, 256, h, k), acc);
            grow2[h] = gelu_f(acc);
        }
        __syncthreads();
        for (int n = t; n < 64; n += NTH) {
            float acc = 0.0f;
            for (int k = 0; k < 256; k++)
                acc = fmaf(grow2[k], wval(wWB, 64, n, k), acc);
            Wt[(size_t)gr*64+n] = acc;
        }
        __syncthreads();
    }
#endif
}

// ---------------------------------------------------------------------------
// pfff1: PF(block0) + FF1GW(block1) fused. X stays in TMEM.
// ---------------------------------------------------------------------------
__global__ __launch_bounds__(NTH)
void pfff1_kernel(const float* __restrict__ Wt, const char* __restrict__ sg,
                  const float* __restrict__ Hf, const char* __restrict__ wFF2,
                  const float* __restrict__ bias2,
                  const char* __restrict__ wF1n, const float* __restrict__ bias1n,
                  const char* __restrict__ wWAn, const char* __restrict__ wWBn,
                  float* __restrict__ HfOut, float* __restrict__ WtOut, int M)
{
#if TC05_OK
    extern __shared__ __align__(1024) char sm[];
    const int t = threadIdx.x, w = t >> 5, lane = t & 31;
    const int row0 = blockIdx.x * 128;
    const uint32_t sb = smem_to_u32(sm);

    if (w == 0) TCGEN05_ALLOC(sb + 0, 512);
    if (t == 0) {
        MBARRIER_INIT(sb + 8, 1);  MBARRIER_INIT(sb + 16, 1);
        MBARRIER_INIT(sb + 24, 1); MBARRIER_INIT(sb + 32, 1);
    }
    __syncthreads();
    uint32_t tmem;
    asm volatile("ld.shared.b32 %0, [%1];" : "=r"(tmem) : "r"(sb + 0));
    const uint32_t idesc = IDESC(256);
    int fu[2] = {0, 0}, mu[2] = {0, 0};

    // PF stage 1: D0 = Wt @ Sg^T (single chunk)
    {
        if (t < 32 && elect_one_pred()) {
            MBAR_EXPECT_TX(sb + FMB(0), 65536);
            BULK_G2S(sb + AOFF(1), sg, 65536, sb + FMB(0));
        }
        float4 va[AITER];
        loadA4(va, Wt, row0, M, 64, 0, t);
        storeA4<false>(sm + AOFF(0), va, t);
        FENCE_ASYNC();
        __syncthreads();
        if (t < 32 && elect_one_pred()) {
            MBARRIER_WAIT_PARITY(sb + FMB(0), fu[0] & 1);
            mma_chunk(tmem, sb + AOFF(0), sb + AOFF(1), 16384, 32768, idesc, true);
            TCGEN05_COMMIT(sb + 8);
        }
        fu[0]++; mu[0]++;
    }
    MBARRIER_WAIT_PARITY(sb + 8, (mu[0] - 1) & 1);
    TCGEN05_FENCE_AFTER();
    __syncthreads();

    // PF stage 2: D1 = [gelu(D0) | gelu(Hf)] @ ff2 (8 chunks)
    #pragma unroll 1
    for (int c = 0; c < 8; ++c) {
        const int b = c & 1;
        uint32_t dr[8];
        float4 va[AITER];
        if (c < 4) {
            TCGEN05_LD_X8(dr, tmem + c * 64 + (w >> 2) * 8);
            TCGEN05_WAIT_LD();
        } else {
            loadA4(va, Hf, row0, M, 256, (c - 4) * 64, t);
        }
        if (mu[b] > 0) MBARRIER_WAIT_PARITY(sb + 8 + b * 8, (mu[b] - 1) & 1);
        if (t < 32 && elect_one_pred()) {
            MBAR_EXPECT_TX(sb + FMB(b), 65536);
            BULK_G2S(sb + BOFF(b), wFF2 + (size_t)c * 65536, 65536, sb + FMB(b));
        }
        char* aB = sm + AOFF(b);
        if (c < 4) {
            TCGEN05_FENCE_BEFORE();
            epiA8<true>(aB, dr, w, lane, nullptr, 0, nullptr);
        } else {
            storeA4<true>(aB, va, t);
        }
        FENCE_ASYNC();
        __syncthreads();
        if (t < 32 && elect_one_pred()) {
            MBARRIER_WAIT_PARITY(sb + FMB(b), fu[b] & 1);
            mma_chunk(tmem + 256, sb + AOFF(b), sb + BOFF(b), 16384, 32768, idesc, c == 0);
            TCGEN05_COMMIT(sb + 8 + b * 8);
        }
        fu[b]++; mu[b]++;
    }
    MBARRIER_WAIT_PARITY(sb + 8,  (mu[0] - 1) & 1);
    MBARRIER_WAIT_PARITY(sb + 16, (mu[1] - 1) & 1);
    TCGEN05_FENCE_AFTER();

    // FF1 stage 0': D0 = (D1 + b2) @ ff1n   (A = X from TMEM, no gelu)
    for (int c = 0; c < 4; ++c) {
        const int b = c & 1;
        uint32_t dr[8];
        TCGEN05_LD_X8(dr, tmem + 256 + c * 64 + (w >> 2) * 8);
        TCGEN05_WAIT_LD();
        if (mu[b] > 0) MBARRIER_WAIT_PARITY(sb + 8 + b * 8, (mu[b] - 1) & 1);
        if (t < 32 && elect_one_pred()) {
            MBAR_EXPECT_TX(sb + FMB(b), 65536);
            BULK_G2S(sb + BOFF(b), wF1n + (size_t)c * 65536, 65536, sb + FMB(b));
        }
        TCGEN05_FENCE_BEFORE();
        epiA8<false>(sm + AOFF(b), dr, w, lane, bias2, c * 64, nullptr);
        FENCE_ASYNC();
        __syncthreads();
        if (t < 32 && elect_one_pred()) {
            MBARRIER_WAIT_PARITY(sb + FMB(b), fu[b] & 1);
            mma_chunk(tmem, sb + AOFF(b), sb + BOFF(b), 16384, 32768, idesc, c == 0);
            TCGEN05_COMMIT(sb + 8 + b * 8);
        }
        fu[b]++; mu[b]++;
    }
    MBARRIER_WAIT_PARITY(sb + 8,  (mu[0] - 1) & 1);
    MBARRIER_WAIT_PARITY(sb + 16, (mu[1] - 1) & 1);
    TCGEN05_FENCE_AFTER();

    // FF1 stage 1': D1 = gelu(D0 + b1n) @ wAn ; write HfOut
    {
        const int grow = row0 + (w & 3) * 32 + lane;
        float* HfRow = (grow < M) ? &HfOut[(size_t)grow * 256] : nullptr;
        for (int c = 0; c < 4; ++c) {
            const int b = c & 1;
            uint32_t dr[8];
            TCGEN05_LD_X8(dr, tmem + c * 64 + (w >> 2) * 8);
            TCGEN05_WAIT_LD();
            if (mu[b] > 0) MBARRIER_WAIT_PARITY(sb + 8 + b * 8, (mu[b] - 1) & 1);
            if (t < 32 && elect_one_pred()) {
                MBAR_EXPECT_TX(sb + FMB(b), 65536);
                BULK_G2S(sb + BOFF(b), wWAn + (size_t)c * 65536, 65536, sb + FMB(b));
            }
            TCGEN05_FENCE_BEFORE();
            epiA8<true>(sm + AOFF(b), dr, w, lane, bias1n, c * 64, HfRow);
            FENCE_ASYNC();
            __syncthreads();
            if (t < 32 && elect_one_pred()) {
                MBARRIER_WAIT_PARITY(sb + FMB(b), fu[b] & 1);
                mma_chunk(tmem + 256, sb + AOFF(b), sb + BOFF(b), 16384, 32768, idesc, c == 0);
                TCGEN05_COMMIT(sb + 8 + b * 8);
            }
            fu[b]++; mu[b]++;
        }
    }
    MBARRIER_WAIT_PARITY(sb + 8,  (mu[0] - 1) & 1);
    MBARRIER_WAIT_PARITY(sb + 16, (mu[1] - 1) & 1);
    TCGEN05_FENCE_AFTER();

    // FF1 stage 2': D0(0..63) = gelu(D1) @ wBn
    for (int c = 0; c < 4; ++c) {
        const int b = c & 1;
        uint32_t dr[8];
        TCGEN05_LD_X8(dr, tmem + 256 + c * 64 + (w >> 2) * 8);
        TCGEN05_WAIT_LD();
        if (mu[b] > 0) MBARRIER_WAIT_PARITY(sb + 8 + b * 8, (mu[b] - 1) & 1);
        if (t < 32 && elect_one_pred()) {
            MBAR_EXPECT_TX(sb + FMB(b), 16384);
            BULK_G2S(sb + BOFF(b), wWBn + (size_t)c * 16384, 16384, sb + FMB(b));
        }
        TCGEN05_FENCE_BEFORE();
        epiA8<true>(sm + AOFF(b), dr, w, lane, nullptr, 0, nullptr);
        FENCE_ASYNC();
        __syncthreads();
        if (t < 32 && elect_one_pred()) {
            MBARRIER_WAIT_PARITY(sb + FMB(b), fu[b] & 1);
            mma_chunk(tmem, sb + AOFF(b), sb + BOFF(b), 16384, 8192, IDESC(64), c == 0);
            TCGEN05_COMMIT(sb + 8 + b * 8);
        }
        fu[b]++; mu[b]++;
    }
    MBARRIER_WAIT_PARITY(sb + 8,  (mu[0] - 1) & 1);
    MBARRIER_WAIT_PARITY(sb + 16, (mu[1] - 1) & 1);
    TCGEN05_FENCE_AFTER();

    // epilogue: WtOut from D0 cols 0..63
    {
        int j = w >> 2;
        if (j < 2) {
            uint32_t dr[32];
            TCGEN05_LD_X32(dr, tmem + j * 32);
            TCGEN05_WAIT_LD();
            const int row = row0 + (w & 3) * 32 + lane;
            if (row < M) {
                #pragma unroll
                for (int c4 = 0; c4 < 8; c4++)
                    *reinterpret_cast<float4*>(&WtOut[(size_t)row * 64 + j * 32 + c4 * 4]) =
                        make_float4(__uint_as_float(dr[c4*4]),   __uint_as_float(dr[c4*4+1]),
                                    __uint_as_float(dr[c4*4+2]), __uint_as_float(dr[c4*4+3]));
            }
        }
    }
    __syncthreads();
    if (w == 0) TCGEN05_DEALLOC(tmem, 512);
#else
    __shared__ float prow[256], xrow[256], hrow[256], grow2[256];
    const int row0 = blockIdx.x * 128;
    const int t = threadIdx.x;
    for (int r = 0; r < 128; r++) {
        int gr = row0 + r;
        if (gr >= M) break;
        for (int n = t; n < 256; n += NTH) {
            float acc = 0.0f;
            for (int k = 0; k < 64; k++)
                acc = fmaf(Wt[(size_t)gr*64+k], wval(sg, 256, n, k), acc);
            prow[n] = gelu_f(acc);
        }
        __syncthreads();
        for (int n = t; n < 256; n += NTH) {
            float acc = bias2[n];
            for (int k = 0; k < 256; k++)
                acc = fmaf(prow[k], wval(wFF2, 256, n, k), acc);
            for (int k = 0; k < 256; k++)
                acc = fmaf(gelu_f(Hf[(size_t)gr*256+k]), wval(wFF2, 256, n, 256 + k), acc);
            xrow[n] = acc;
        }
        __syncthreads();
        for (int h = t; h < 256; h += NTH) {
            float acc = bias1n[h];
            for (int k = 0; k < 256; k++)
                acc = fmaf(xrow[k], wval(wF1n, 256, h, k), acc);
            float f = gelu_f(acc);
            hrow[h] = f;
            HfOut[(size_t)gr*256+h] = f;
        }
        __syncthreads();
        for (int h = t; h < 256; h += NTH) {
            float acc = 0.0f;
            for (int k = 0; k < 256; k++)
                acc = fmaf(hrow[k], wval(wWAn, 256, h, k), acc);
            grow2[h] = gelu_f(acc);
        }
        __syncthreads();
        for (int n = t; n < 64; n += NTH) {
            float acc = 0.0f;
            for (int k = 0; k < 256; k++)
                acc = fmaf(grow2[k], wval(wWBn, 64, n, k), acc);
            WtOut[(size_t)gr*64+n] = acc;
        }
        __syncthreads();
    }
#endif
}

// ---------------------------------------------------------------------------
// PF (block 1, LAST): mean-partials of X into mp.
// ---------------------------------------------------------------------------
__global__ __launch_bounds__(NTH)
void gemmPF_last_kernel(const float* __restrict__ Wt, const char* __restrict__ sg,
                        const float* __restrict__ Hf, const char* __restrict__ wFF2,
                        const float* __restrict__ bias2, float* __restrict__ mp, int M)
{
#if TC05_OK
    extern __shared__ __align__(1024) char sm[];
    const int t = threadIdx.x, w = t >> 5, lane = t & 31;
    const int row0 = blockIdx.x * 128;
    const uint32_t sb = smem_to_u32(sm);

    if (w == 0) TCGEN05_ALLOC(sb + 0, 512);
    if (t == 0) {
        MBARRIER_INIT(sb + 8, 1);  MBARRIER_INIT(sb + 16, 1);
        MBARRIER_INIT(sb + 24, 1); MBARRIER_INIT(sb + 32, 1);
    }
    __syncthreads();
    uint32_t tmem;
    asm volatile("ld.shared.b32 %0, [%1];" : "=r"(tmem) : "r"(sb + 0));
    const uint32_t idesc = IDESC(256);
    int fu[2] = {0, 0}, mu[2] = {0, 0};

    {
        if (t < 32 && elect_one_pred()) {
            MBAR_EXPECT_TX(sb + FMB(0), 65536);
            BULK_G2S(sb + AOFF(1), sg, 65536, sb + FMB(0));
        }
        float4 va[AITER];
        loadA4(va, Wt, row0, M, 64, 0, t);
        storeA4<false>(sm + AOFF(0), va, t);
        FENCE_ASYNC();
        __syncthreads();
        if (t < 32 && elect_one_pred()) {
            MBARRIER_WAIT_PARITY(sb + FMB(0), fu[0] & 1);
            mma_chunk(tmem, sb + AOFF(0), sb + AOFF(1), 16384, 32768, idesc, true);
            TCGEN05_COMMIT(sb + 8);
        }
        fu[0]++; mu[0]++;
    }
    MBARRIER_WAIT_PARITY(sb + 8, (mu[0] - 1) & 1);
    TCGEN05_FENCE_AFTER();
    __syncthreads();

    #pragma unroll 1
    for (int c = 0; c < 8; ++c) {
        const int b = c & 1;
        uint32_t dr[8];
        float4 va[AITER];
        if (c < 4) {
            TCGEN05_LD_X8(dr, tmem + c * 64 + (w >> 2) * 8);
            TCGEN05_WAIT_LD();
        } else {
            loadA4(va, Hf, row0, M, 256, (c - 4) * 64, t);
        }
        if (mu[b] > 0) MBARRIER_WAIT_PARITY(sb + 8 + b * 8, (mu[b] - 1) & 1);
        if (t < 32 && elect_one_pred()) {
            MBAR_EXPECT_TX(sb + FMB(b), 65536);
            BULK_G2S(sb + BOFF(b), wFF2 + (size_t)c * 65536, 65536, sb + FMB(b));
        }
        char* aB = sm + AOFF(b);
        if (c < 4) {
            TCGEN05_FENCE_BEFORE();
            epiA8<true>(aB, dr, w, lane, nullptr, 0, nullptr);
        } else {
            storeA4<true>(aB, va, t);
        }
        FENCE_ASYNC();
        __syncthreads();
        if (t < 32 && elect_one_pred()) {
            MBARRIER_WAIT_PARITY(sb + FMB(b), fu[b] & 1);
            mma_chunk(tmem + 256, sb + AOFF(b), sb + BOFF(b), 16384, 32768, idesc, c == 0);
            TCGEN05_COMMIT(sb + 8 + b * 8);
        }
        fu[b]++; mu[b]++;
    }
    MBARRIER_WAIT_PARITY(sb + 8,  (mu[0] - 1) & 1);
    MBARRIER_WAIT_PARITY(sb + 16, (mu[1] - 1) & 1);
    TCGEN05_FENCE_AFTER();

    float* mp_s = reinterpret_cast<float*>(sm + 1024);
    const int row = row0 + (w & 3) * 32 + lane;
    {
        const int j = w >> 2;
        uint32_t dr[32];
        TCGEN05_LD_X32(dr, tmem + 256 + j * 32);
        TCGEN05_WAIT_LD();
        #pragma unroll
        for (int c4 = 0; c4 < 8; c4++) {
            float4 v;
            v.x = __uint_as_float(dr[c4*4])   + bias2[j*32 + c4*4];
            v.y = __uint_as_float(dr[c4*4+1]) + bias2[j*32 + c4*4+1];
            v.z = __uint_as_float(dr[c4*4+2]) + bias2[j*32 + c4*4+2];
            v.w = __uint_as_float(dr[c4*4+3]) + bias2[j*32 + c4*4+3];
            if (row >= M) { v.x = v.y = v.z = v.w = 0.f; }
            v.x = wsum(v.x); v.y = wsum(v.y); v.z = wsum(v.z); v.w = wsum(v.w);
            if (lane == 0)
                *reinterpret_cast<float4*>(&mp_s[(w & 3) * 256 + j * 32 + c4 * 4]) = v;
        }
    }
    __syncthreads();
    if (t < 256)
        mp[(size_t)blockIdx.x * 256 + t] =
            mp_s[t] + mp_s[256 + t] + mp_s[512 + t] + mp_s[768 + t];
    __syncthreads();
    if (w == 0) TCGEN05_DEALLOC(tmem, 512);
#else
    __shared__ float prow[256];
    __shared__ float msum[256];
    const int row0 = blockIdx.x * 128;
    const int t = threadIdx.x;
    if (t < 256) msum[t] = 0.f;
    __syncthreads();
    for (int r = 0; r < 128; r++) {
        int gr = row0 + r;
        if (gr >= M) break;
        for (int n = t; n < 256; n += NTH) {
            float acc = 0.0f;
            for (int k = 0; k < 64; k++)
                acc = fmaf(Wt[(size_t)gr*64+k], wval(sg, 256, n, k), acc);
            prow[n] = gelu_f(acc);
        }
        __syncthreads();
        for (int n = t; n < 256; n += NTH) {
            float acc = bias2[n];
            for (int k = 0; k < 256; k++)
                acc = fmaf(prow[k], wval(wFF2, 256, n, k), acc);
            for (int k = 0; k < 256; k++)
                acc = fmaf(gelu_f(Hf[(size_t)gr*256+k]), wval(wFF2, 256, n, 256 + k), acc);
            msum[n] += acc;
        }
        __syncthreads();
    }
    if (t < 256) mp[(size_t)blockIdx.x * 256 + t] = msum[t];
#endif
}

// ---------------------------------------------------------------------------
// spartial05: S partials via tcgen05 (unchanged).
// ---------------------------------------------------------------------------
__global__ __launch_bounds__(NTH)
void spartial05_kernel(const float* __restrict__ Hf, const float* __restrict__ Wt,
                       float* __restrict__ part, int N)
{
#if TC05_OK
    extern __shared__ __align__(1024) char sm[];
    const int t = threadIdx.x, w = t >> 5, lane = t & 31;
    const uint32_t sb = smem_to_u32(sm);
    const int totalChunks = (N + 63) >> 6;
    const int per = (totalChunks + SPGRID - 1) / SPGRID;
    const int cbeg = blockIdx.x * per;
    const int cend = min(totalChunks, cbeg + per);
    const int nch = cend - cbeg;
    float* myPart = part + (size_t)blockIdx.x * HDIM * MDIM;

    if (w == 0) TCGEN05_ALLOC(sb + 0, 128);
    if (t == 0) { MBARRIER_INIT(sb + 8, 1); MBARRIER_INIT(sb + 16, 1); }
    __syncthreads();
    uint32_t tmem;
    asm volatile("ld.shared.b32 %0, [%1];" : "=r"(tmem) : "r"(sb + 0));

    if (nch > 0) {
        const uint32_t idesc = IDESC(64);
        for (int ci = 0; ci < nch; ++ci) {
            const int b = ci & 1;
            if ((ci >> 1) >= 1) MBARRIER_WAIT_PARITY(sb + 8 + b * 8, ((ci >> 1) - 1) & 1);
            char* buf = sm + 1024 + b * 81920;
            const int rbeg = (cbeg + ci) * 64;

            #pragma unroll
            for (int i = 0; i < 2048 / NTH; i++) {
                int fid = t + i * NTH;
                int kp = fid & 31, hg = fid >> 5;
                int h0 = hg * 4;
                int k0 = rbeg + 2 * kp;
                float4 fa = (k0     < N) ? *reinterpret_cast<const float4*>(&Hf[(size_t)k0 * 256 + h0])
                                         : make_float4(0.f, 0.f, 0.f, 0.f);
                float4 fb = (k0 + 1 < N) ? *reinterpret_cast<const float4*>(&Hf[(size_t)(k0 + 1) * 256 + h0])
                                         : make_float4(0.f, 0.f, 0.f, 0.f);
                char* ah = buf + (h0 >> 7) * 32768;
                int r0 = h0 & 127;
                const float* pa = &fa.x;
                const float* pb = &fb.x;
                #pragma unroll
                for (int j = 0; j < 4; j++) {
                    uint32_t hp, lp;
                    split2(pa[j], pb[j], hp, lp);
                    int off = SWZ((r0 + j) * 128 + kp * 4);
                    *reinterpret_cast<uint32_t*>(ah + off)         = hp;
                    *reinterpret_cast<uint32_t*>(ah + 16384 + off) = lp;
                }
            }
            if (t < 512) {
                int kp = t & 31, mg = t >> 5;
                int m0 = mg * 4;
                int k0 = rbeg + 2 * kp;
                float4 fa = (k0     < N) ? *reinterpret_cast<const float4*>(&Wt[(size_t)k0 * 64 + m0])
                                         : make_float4(0.f, 0.f, 0.f, 0.f);
                float4 fb = (k0 + 1 < N) ? *reinterpret_cast<const float4*>(&Wt[(size_t)(k0 + 1) * 64 + m0])
                                         : make_float4(0.f, 0.f, 0.f, 0.f);
                char* bh = buf + 65536;
                const float* pa = &fa.x;
                const float* pb = &fb.x;
                #pragma unroll
                for (int j = 0; j < 4; j++) {
                    uint32_t hp, lp;
                    split2(pa[j], pb[j], hp, lp);
                    int off = SWZ((m0 + j) * 128 + kp * 4);
                    *reinterpret_cast<uint32_t*>(bh + off)        = hp;
                    *reinterpret_cast<uint32_t*>(bh + 8192 + off) = lp;
                }
            }
            FENCE_ASYNC();
            __syncthreads();
            if (t < 32 && elect_one_pred()) {
                uint32_t aBase = sb + 1024 + b * 81920;
                mma_chunk(tmem,      aBase,         aBase + 65536, 16384, 8192, idesc, ci == 0);
                mma_chunk(tmem + 64, aBase + 32768, aBase + 65536, 16384, 8192, idesc, ci == 0);
                TCGEN05_COMMIT(sb + 8 + b * 8);
            }
        }
        MBARRIER_WAIT_PARITY(sb + 8 + ((nch - 1) & 1) * 8, ((nch - 1) >> 1) & 1);
        TCGEN05_FENCE_AFTER();

        {
            int idx = w >> 2;
            if (idx < 4) {
                int mt = idx >> 1, s = idx & 1;
                uint32_t dr[32];
                TCGEN05_LD_X32(dr, tmem + mt * 64 + s * 32);
                TCGEN05_WAIT_LD();
                int h = mt * 128 + (w & 3) * 32 + lane;
                float* p = myPart + (size_t)h * 64 + s * 32;
                #pragma unroll
                for (int c4 = 0; c4 < 8; c4++)
                    *reinterpret_cast<float4*>(&p[c4 * 4]) =
                        make_float4(__uint_as_float(dr[c4*4]),   __uint_as_float(dr[c4*4+1]),
                                    __uint_as_float(dr[c4*4+2]), __uint_as_float(dr[c4*4+3]));
            }
        }
    } else {
        for (int i = t; i < HDIM * MDIM; i += NTH)
            myPart[i] = 0.0f;
    }
    __syncthreads();
    if (w == 0) TCGEN05_DEALLOC(tmem, 128);
#else
    const int t = threadIdx.x;
    const int hq = t & 127, mq = (t >> 7) & 3;
    const int totalChunks = (N + 63) >> 6;
    const int per = (totalChunks + SPGRID - 1) / SPGRID;
    const int rbeg = blockIdx.x * per * 64;
    const int rend = min(N, (blockIdx.x + 1) * per * 64);
    const int half = t >> 9;
    if (half == 0) {
        float accF[2][16];
        #pragma unroll
        for (int j = 0; j < 2; j++)
            #pragma unroll
            for (int i = 0; i < 16; i++) accF[j][i] = 0.0f;
        for (int r = rbeg; r < rend; r++) {
            float a0 = Hf[(size_t)r * HDIM + hq * 2];
            float a1 = Hf[(size_t)r * HDIM + hq * 2 + 1];
            #pragma unroll
            for (int i = 0; i < 16; i++) {
                float wv = Wt[(size_t)r * MDIM + mq * 16 + i];
                accF[0][i] = fmaf(a0, wv, accF[0][i]);
                accF[1][i] = fmaf(a1, wv, accF[1][i]);
            }
        }
        float* myPart = part + (size_t)blockIdx.x * HDIM * MDIM;
        #pragma unroll
        for (int j = 0; j < 2; j++)
            #pragma unroll
            for (int i = 0; i < 16; i++)
                myPart[(size_t)(hq * 2 + j) * MDIM + mq * 16 + i] = accF[j][i];
    }
#endif
}

// Sum SPGRID partials, gelu, emit Sg^T pre-swizzled tile.
__global__ __launch_bounds__(256)
void sfinal_kernel(const float* __restrict__ part, char* __restrict__ sg)
{
    int idx = blockIdx.x * 256 + threadIdx.x;   // h*64+m
    float s = 0.0f;
    for (int p = 0; p < SPGRID; p++)
        s += part[(size_t)p * HDIM * MDIM + idx];
    float g = gelu_f(s);
    __nv_bfloat16 h = __float2bfloat16_rn(g);
    __nv_bfloat16 l = __float2bfloat16_rn(g - __bfloat162float(h));
    int hh = idx >> 6, m = idx & 63;
    uint32_t so = SWZ(hh * 128 + m * 2);
    *reinterpret_cast<__nv_bfloat16*>(sg + so)         = h;
    *reinterpret_cast<__nv_bfloat16*>(sg + 32768 + so) = l;
}

// weight prep: single launch, chunked swizzled tile layout
__constant__ int c_wOff[9] = {0, 65536, 131072, 147456, 278528, 344064, 409600, 425984, 557056};
__constant__ int c_wK[8]   = {256, 256, 256, 512, 256, 256, 256, 512};
__constant__ int c_wNc[8]  = {256, 256, 64, 256, 256, 256, 64, 256};
__constant__ int c_wB[8]   = {0, 262144, 524288, 589824, 1114112, 1376256, 1638400, 1703936};
__global__ void transsplit_all(const float* s0, const float* s1, const float* s2, const float* s3,
                               const float* s4, const float* s5, const float* s6, const float* s7,
                               char* __restrict__ wsw)
{
    int idx = blockIdx.x * 256 + threadIdx.x;
    if (idx >= 557056) return;
    int i = 0;
    while (idx >= c_wOff[i + 1]) i++;
    const float* srcs[8] = {s0, s1, s2, s3, s4, s5, s6, s7};
    int local = idx - c_wOff[i];
    int K = c_wK[i], Nc = c_wNc[i];
    int n = local / K, k = local % K;
    float v = srcs[i][(size_t)k * Nc + n];
    __nv_bfloat16 h = __float2bfloat16_rn(v);
    __nv_bfloat16 l = __float2bfloat16_rn(v - __bfloat162float(h));
    int ch = k >> 6, kk = k & 63;
    char* base = wsw + c_wB[i] + (size_t)ch * (Nc * 256);
    uint32_t so = SWZ(n * 128 + kk * 2);
    *reinterpret_cast<__nv_bfloat16*>(base + so)            = h;
    *reinterpret_cast<__nv_bfloat16*>(base + Nc * 128 + so) = l;
}

// head: out = (sum of per-CTA partials / N) @ head_w + head_b
__global__ __launch_bounds__(256)
void head_kernel(const float* __restrict__ part, const float* __restrict__ hw,
                 const float* __restrict__ hb, float* __restrict__ out,
                 int N, int gridN)
{
    __shared__ float s[HDIM];
    int t = threadIdx.x;
    float a = 0.0f;
    for (int p = 0; p < gridN; p++) a += part[(size_t)p * HDIM + t];
    s[t] = a * (1.0f / (float)N);
    __syncthreads();
    if (t < 64) {
        float o = hb[t];
        #pragma unroll 8
        for (int h = 0; h < HDIM; h++)
            o = fmaf(s[h], hw[h * 64 + t], o);
        out[t] = o;
    }
}

// ---------------------------------------------------------------------------
// Host
// ---------------------------------------------------------------------------
extern "C" void kernel_launch(void* const* d_in, const int* in_sizes, int n_in,
                              void* d_out, int out_size)
{
    const float* x      = (const float*)d_in[0];
    const float* ff1_w0 = (const float*)d_in[2];
    const float* ff1_b0 = (const float*)d_in[3];
    const float* wA0    = (const float*)d_in[4];
    const float* wB0    = (const float*)d_in[5];
    const float* ff2_w0 = (const float*)d_in[6];
    const float* ff2_b0 = (const float*)d_in[7];
    const float* ff1_w1 = (const float*)d_in[8];
    const float* ff1_b1 = (const float*)d_in[9];
    const float* wA1    = (const float*)d_in[10];
    const float* wB1    = (const float*)d_in[11];
    const float* ff2_w1 = (const float*)d_in[12];
    const float* ff2_b1 = (const float*)d_in[13];
    const float* head_w = (const float*)d_in[14];
    const float* head_b = (const float*)d_in[15];
    float* out = (float*)d_out;

    const int N = in_sizes[0] / HDIM;
    const int grid = (N + 127) / 128;

    float *pHf, *pWt, *pPart, *pMp;
    char *pWsw, *pSg;
    cudaGetSymbolAddress((void**)&pHf,   g_Hf);
    cudaGetSymbolAddress((void**)&pWt,   g_Wt);
    cudaGetSymbolAddress((void**)&pPart, g_part);
    cudaGetSymbolAddress((void**)&pMp,   g_mp);
    cudaGetSymbolAddress((void**)&pWsw,  g_wsw);
    cudaGetSymbolAddress((void**)&pSg,   g_sgsw);

    cudaFuncSetAttribute(ff1gw_kernel,      cudaFuncAttributeMaxDynamicSharedMemorySize, FSMEM);
    cudaFuncSetAttribute(pfff1_kernel,      cudaFuncAttributeMaxDynamicSharedMemorySize, FSMEM);
    cudaFuncSetAttribute(gemmPF_last_kernel,cudaFuncAttributeMaxDynamicSharedMemorySize, FSMEM);
    cudaFuncSetAttribute(spartial05_kernel, cudaFuncAttributeMaxDynamicSharedMemorySize, SPSMEM);

    transsplit_all<<<(557056 + 255) / 256, 256>>>(ff1_w0, wA0, wB0, ff2_w0,
                                                  ff1_w1, wA1, wB1, ff2_w1, pWsw);

    // block 0 front half
    ff1gw_kernel<<<grid, NTH, FSMEM>>>(x,
        pWsw + WB_FF1, ff1_b0, pWsw + WB_WA, pWsw + WB_WB, pHf, pWt, N);
    spartial05_kernel<<<SPGRID, NTH, SPSMEM>>>(pHf, pWt, pPart, N);
    sfinal_kernel<<<64, 256>>>(pPart, pSg);

    // fused: PF(block0) + FF1GW(block1); X never hits HBM
    pfff1_kernel<<<grid, NTH, FSMEM>>>(pWt, pSg, pHf,
        pWsw + WB_FF2, ff2_b0,
        pWsw + WB_BLK + WB_FF1, ff1_b1,
        pWsw + WB_BLK + WB_WA, pWsw + WB_BLK + WB_WB,
        pHf, pWt, N);
    spartial05_kernel<<<SPGRID, NTH, SPSMEM>>>(pHf, pWt, pPart, N);
    sfinal_kernel<<<64, 256>>>(pPart, pSg);

    // block 1 back half with fused mean partials
    gemmPF_last_kernel<<<grid, NTH, FSMEM>>>(pWt, pSg, pHf,
        pWsw + WB_BLK + WB_FF2, ff2_b1, pMp, N);

    head_kernel<<<1, 256>>>(pMp, head_w, head_b, out, N, grid);
}